// round 4
// baseline (speedup 1.0000x reference)
#include <cuda_runtime.h>
#include <math.h>

// ---------------- problem dims ----------------
#define BB   512
#define LL   128
#define HH   768
#define LHID 256
#define G4   1024   // 4*LHID

// ---------------- device scratch (no allocs allowed) ----------------
__device__ float g_gatesx[(size_t)BB * LL * G4];   // 256 MB: x @ w_ih^T + biases
__device__ float g_gates [(size_t)BB * G4];        // per-step gate buffer
__device__ float g_h     [(size_t)BB * LHID];
__device__ float g_c     [(size_t)BB * LHID];
__device__ float g_hsum  [(size_t)BB * LHID];
__device__ float g_y1    [(size_t)BB * 256 * 64];  // after conv1+pool+relu
__device__ float g_y2    [(size_t)BB * 64 * 32];   // after conv2+pool+relu
__device__ float g_y3    [(size_t)BB * 256 * 16];  // after conv3+pool+relu
__device__ float g_feat  [(size_t)BB * 256];       // after conv4+relu (flattened)

// =====================================================================
// Generic SGEMM: C[m,n] = sum_k A[m,k]*B[n,k] (+bias0[n]) (+bias1[n]) (+D[m,n])
// BM=BN=64, BK=16, 256 threads, 4x4 register tile per thread.
// =====================================================================
__global__ __launch_bounds__(256) void sgemm_nt(
    int M, int N, int K,
    const float* __restrict__ A, int lda,
    const float* __restrict__ B, int ldb,
    const float* __restrict__ D, int ldd,
    const float* __restrict__ bias0,
    const float* __restrict__ bias1,
    float* __restrict__ C, int ldc)
{
    __shared__ float As[16][64];
    __shared__ float Bs[16][64];
    const int tid = threadIdx.x;
    const int m0 = blockIdx.y * 64;
    const int n0 = blockIdx.x * 64;
    const int lr = tid >> 2;          // 0..63 : tile row for loads
    const int lc = (tid & 3) << 2;    // 0,4,8,12 : k offset for loads
    const int tx = tid & 15;
    const int ty = tid >> 4;

    float acc[4][4];
#pragma unroll
    for (int i = 0; i < 4; i++)
#pragma unroll
        for (int j = 0; j < 4; j++) acc[i][j] = 0.f;

    const float* Ap = A + (size_t)(m0 + lr) * lda + lc;
    const float* Bp = B + (size_t)(n0 + lr) * ldb + lc;

    for (int k0 = 0; k0 < K; k0 += 16) {
        float4 av = *(const float4*)(Ap + k0);
        float4 bv = *(const float4*)(Bp + k0);
        As[lc + 0][lr] = av.x; As[lc + 1][lr] = av.y;
        As[lc + 2][lr] = av.z; As[lc + 3][lr] = av.w;
        Bs[lc + 0][lr] = bv.x; Bs[lc + 1][lr] = bv.y;
        Bs[lc + 2][lr] = bv.z; Bs[lc + 3][lr] = bv.w;
        __syncthreads();
#pragma unroll
        for (int kk = 0; kk < 16; kk++) {
            float4 a = *(const float4*)&As[kk][ty << 2];
            float4 b = *(const float4*)&Bs[kk][tx << 2];
            float ar[4] = {a.x, a.y, a.z, a.w};
            float br[4] = {b.x, b.y, b.z, b.w};
#pragma unroll
            for (int i = 0; i < 4; i++)
#pragma unroll
                for (int j = 0; j < 4; j++)
                    acc[i][j] += ar[i] * br[j];
        }
        __syncthreads();
    }

#pragma unroll
    for (int i = 0; i < 4; i++) {
        int m = m0 + (ty << 2) + i;
#pragma unroll
        for (int j = 0; j < 4; j++) {
            int n = n0 + (tx << 2) + j;
            float v = acc[i][j];
            if (bias0) v += bias0[n];
            if (bias1) v += bias1[n];
            if (D)     v += D[(size_t)m * ldd + n];
            C[(size_t)m * ldc + n] = v;
        }
    }
}

// =====================================================================
// LSTM pointwise cell update (PyTorch gate order i,f,g,o)
// =====================================================================
__global__ void lstm_init_kernel(float* h, float* c, float* s)
{
    int idx = blockIdx.x * 256 + threadIdx.x;
    h[idx] = 0.f; c[idx] = 0.f; s[idx] = 0.f;
}

__device__ __forceinline__ float sigf(float x) { return 1.f / (1.f + expf(-x)); }

__global__ void lstm_cell_kernel(const float* __restrict__ gates,
                                 float* __restrict__ h,
                                 float* __restrict__ c,
                                 float* __restrict__ hsum)
{
    int idx = blockIdx.x * 256 + threadIdx.x;      // 512*256
    int b = idx >> 8, j = idx & 255;
    const float* g = gates + (size_t)b * G4;
    float si = sigf(g[j]);
    float sf = sigf(g[256 + j]);
    float tg = tanhf(g[512 + j]);
    float so = sigf(g[768 + j]);
    float cn = sf * c[idx] + si * tg;
    c[idx] = cn;
    float hn = so * tanhf(cn);
    h[idx] = hn;
    hsum[idx] += hn;
}

// =====================================================================
// conv1: x[B,128,768] -> conv(k=7,pad=3,Cout=256) + bias -> pool2 -> relu
// out y1[B,256,64].  Block = (b, co-group of 64). 256 thr.
// smem: xs[32 ci][137 pitch, 134 used], ws[64 co][224 = 32ci*7kw]
// thread: lane covers conv pos {lane+32i}, cog=tid>>5 covers co {cog+8j}
// pooling of adjacent positions via shfl_xor(.,1).
// =====================================================================
__global__ __launch_bounds__(256) void conv1_kernel(
    const float* __restrict__ x, const float* __restrict__ w,
    const float* __restrict__ bias, float* __restrict__ out)
{
    extern __shared__ float sm[];
    float* xs = sm;             // 32*137
    float* ws = sm + 32 * 137;  // 64*224
    const int b   = blockIdx.x;
    const int co0 = blockIdx.y * 64;
    const int tid = threadIdx.x;
    const int lane = tid & 31;
    const int cog  = tid >> 5;  // 0..7

    float acc[8][4];
#pragma unroll
    for (int j = 0; j < 8; j++)
#pragma unroll
        for (int i = 0; i < 4; i++) acc[j][i] = 0.f;

    const float* xb = x + (size_t)b * LL * HH;

    for (int ci0 = 0; ci0 < HH; ci0 += 32) {
        // stage x window (seq pos -3..130 -> s=0..133), coalesced over ci
        for (int idx = tid; idx < 32 * 134; idx += 256) {
            int cil = idx & 31, s = idx >> 5;
            int p = s - 3;
            xs[cil * 137 + s] =
                (p >= 0 && p < LL) ? xb[(size_t)p * HH + ci0 + cil] : 0.f;
        }
        // stage weights: ws[col][r], r = cil*7+kw (contiguous in gmem per col)
        for (int idx = tid; idx < 64 * 224; idx += 256) {
            int col = idx / 224, r = idx - col * 224;
            ws[idx] = w[(size_t)(co0 + col) * (HH * 7) + ci0 * 7 + r];
        }
        __syncthreads();

        for (int ci = 0; ci < 32; ci++) {
            const float* xr = &xs[ci * 137 + lane];
            const float* wr = &ws[cog * 224 + ci * 7];
#pragma unroll
            for (int kw = 0; kw < 7; kw++) {
                float xv0 = xr[kw];
                float xv1 = xr[kw + 32];
                float xv2 = xr[kw + 64];
                float xv3 = xr[kw + 96];
#pragma unroll
                for (int j = 0; j < 8; j++) {
                    float wv = wr[j * (8 * 224) + kw];  // ws[cog+8j][ci*7+kw]
                    acc[j][0] += wv * xv0;
                    acc[j][1] += wv * xv1;
                    acc[j][2] += wv * xv2;
                    acc[j][3] += wv * xv3;
                }
            }
        }
        __syncthreads();
    }

#pragma unroll
    for (int j = 0; j < 8; j++) {
        int co = co0 + cog + 8 * j;
        float bv = bias[co];
#pragma unroll
        for (int i = 0; i < 4; i++) {
            float v = acc[j][i] + bv;
            float o = __shfl_xor_sync(0xffffffffu, v, 1);
            float m = fmaxf(v, o);
            if (!(lane & 1)) {
                int q = (lane >> 1) + 16 * i;        // pooled position 0..63
                out[(size_t)b * 256 * 64 + (size_t)co * 64 + q] = fmaxf(m, 0.f);
            }
        }
    }
}

// =====================================================================
// conv2: y1[B,256,64] -> conv(k=5,pad=2,Cout=64)+bias -> pool2 -> relu
// out y2[B,64,32]. Block per b. smem: xs[32][69], ws[64][160].
// =====================================================================
__global__ __launch_bounds__(256) void conv2_kernel(
    const float* __restrict__ in, const float* __restrict__ w,
    const float* __restrict__ bias, float* __restrict__ out)
{
    extern __shared__ float sm[];
    float* xs = sm;            // 32*69
    float* ws = sm + 32 * 69;  // 64*160
    const int b = blockIdx.x;
    const int tid = threadIdx.x;
    const int lane = tid & 31;
    const int cog  = tid >> 5;  // co = cog + 8j, j 0..7

    float acc[8][2];
#pragma unroll
    for (int j = 0; j < 8; j++) { acc[j][0] = 0.f; acc[j][1] = 0.f; }

    const float* ib = in + (size_t)b * 256 * 64;

    for (int ci0 = 0; ci0 < 256; ci0 += 32) {
        for (int idx = tid; idx < 32 * 68; idx += 256) {
            int cil = idx / 68, s = idx - cil * 68;
            int p = s - 2;
            xs[cil * 69 + s] =
                (p >= 0 && p < 64) ? ib[(size_t)(ci0 + cil) * 64 + p] : 0.f;
        }
        for (int idx = tid; idx < 64 * 160; idx += 256) {
            int col = idx / 160, r = idx - col * 160;
            ws[idx] = w[(size_t)col * (256 * 5) + ci0 * 5 + r];
        }
        __syncthreads();

        for (int ci = 0; ci < 32; ci++) {
            const float* xr = &xs[ci * 69 + lane];
            const float* wr = &ws[cog * 160 + ci * 5];
#pragma unroll
            for (int kw = 0; kw < 5; kw++) {
                float xv0 = xr[kw];
                float xv1 = xr[kw + 32];
#pragma unroll
                for (int j = 0; j < 8; j++) {
                    float wv = wr[j * (8 * 160) + kw];
                    acc[j][0] += wv * xv0;
                    acc[j][1] += wv * xv1;
                }
            }
        }
        __syncthreads();
    }

#pragma unroll
    for (int j = 0; j < 8; j++) {
        int co = cog + 8 * j;
        float bv = bias[co];
#pragma unroll
        for (int i = 0; i < 2; i++) {
            float v = acc[j][i] + bv;
            float o = __shfl_xor_sync(0xffffffffu, v, 1);
            float m = fmaxf(v, o);
            if (!(lane & 1)) {
                int q = (lane >> 1) + 16 * i;   // 0..31
                out[(size_t)b * 64 * 32 + (size_t)co * 32 + q] = fmaxf(m, 0.f);
            }
        }
    }
}

// =====================================================================
// conv3: y2[B,64,32] -> conv(k=3,pad=1,Cout=256)+bias -> pool2 -> relu
// out y3[B,256,16]. Block = (b, co-group of 128). smem: xs[64][37], ws[128][192]
// =====================================================================
__global__ __launch_bounds__(256) void conv3_kernel(
    const float* __restrict__ in, const float* __restrict__ w,
    const float* __restrict__ bias, float* __restrict__ out)
{
    extern __shared__ float sm[];
    float* xs = sm;            // 64*37 (34 used)
    float* ws = sm + 64 * 37;  // 128*192
    const int b   = blockIdx.x;
    const int co0 = blockIdx.y * 128;
    const int tid = threadIdx.x;
    const int lane = tid & 31;      // conv position 0..31
    const int cog  = tid >> 5;      // co = co0 + cog + 8j, j 0..15

    float acc[16];
#pragma unroll
    for (int j = 0; j < 16; j++) acc[j] = 0.f;

    const float* ib = in + (size_t)b * 64 * 32;

    for (int idx = tid; idx < 64 * 34; idx += 256) {
        int cil = idx / 34, s = idx - cil * 34;
        int p = s - 1;
        xs[cil * 37 + s] = (p >= 0 && p < 32) ? ib[(size_t)cil * 32 + p] : 0.f;
    }
    for (int idx = tid; idx < 128 * 192; idx += 256) {
        int col = idx / 192, r = idx - col * 192;
        ws[idx] = w[(size_t)(co0 + col) * 192 + r];
    }
    __syncthreads();

    for (int ci = 0; ci < 64; ci++) {
        const float* xr = &xs[ci * 37 + lane];
        float xv0 = xr[0], xv1 = xr[1], xv2 = xr[2];
        const float* wr = &ws[cog * 192 + ci * 3];
#pragma unroll
        for (int j = 0; j < 16; j++) {
            const float* wj = wr + j * (8 * 192);
            acc[j] += wj[0] * xv0 + wj[1] * xv1 + wj[2] * xv2;
        }
    }

#pragma unroll
    for (int j = 0; j < 16; j++) {
        int co = co0 + cog + 8 * j;
        float v = acc[j] + bias[co];
        float o = __shfl_xor_sync(0xffffffffu, v, 1);
        float m = fmaxf(v, o);
        if (!(lane & 1)) {
            int q = lane >> 1;   // 0..15
            out[(size_t)b * 256 * 16 + (size_t)co * 16 + q] = fmaxf(m, 0.f);
        }
    }
}

// =====================================================================
// conv4 (k=1, 256->16) + relu + flatten: feat[b, co*16 + pos]
// =====================================================================
__global__ __launch_bounds__(256) void conv4_kernel(
    const float* __restrict__ in, const float* __restrict__ w,
    const float* __restrict__ bias, float* __restrict__ out)
{
    __shared__ float xsh[4096];
    __shared__ float wsh[4096];
    int b = blockIdx.x, tid = threadIdx.x;
    const float* ib = in + (size_t)b * 4096;
    for (int i = tid; i < 4096; i += 256) { xsh[i] = ib[i]; wsh[i] = w[i]; }
    __syncthreads();
    int co = tid >> 4, p = tid & 15;
    float acc = bias[co];
#pragma unroll 8
    for (int ci = 0; ci < 256; ci++)
        acc += xsh[ci * 16 + p] * wsh[co * 256 + ci];
    out[(size_t)b * 256 + co * 16 + p] = fmaxf(acc, 0.f);
}

// =====================================================================
// MLP head: zin = [hsum/128 , feat] ; fc1(512->128) relu; fc2(128->32) relu;
// fc3(32->2) relu. One block per batch row.
// =====================================================================
__global__ __launch_bounds__(128) void mlp_kernel(
    const float* __restrict__ hsum, const float* __restrict__ feat,
    const float* __restrict__ w1, const float* __restrict__ b1,
    const float* __restrict__ w2, const float* __restrict__ b2,
    const float* __restrict__ w3, const float* __restrict__ b3,
    float* __restrict__ out)
{
    __shared__ float zin[512];
    __shared__ float z1[128];
    __shared__ float z2[32];
    int b = blockIdx.x, tid = threadIdx.x;
    for (int i = tid; i < 256; i += 128) {
        zin[i]       = hsum[(size_t)b * 256 + i] * (1.f / 128.f);
        zin[256 + i] = feat[(size_t)b * 256 + i];
    }
    __syncthreads();
    {
        const float* wr = w1 + (size_t)tid * 512;
        float acc = 0.f;
#pragma unroll 4
        for (int k = 0; k < 512; k += 4) {
            float4 wv = *(const float4*)(wr + k);
            float4 xv = *(const float4*)(&zin[k]);
            acc += wv.x * xv.x + wv.y * xv.y + wv.z * xv.z + wv.w * xv.w;
        }
        z1[tid] = fmaxf(acc + b1[tid], 0.f);
    }
    __syncthreads();
    if (tid < 32) {
        const float* wr = w2 + (size_t)tid * 128;
        float acc = 0.f;
#pragma unroll
        for (int k = 0; k < 128; k += 4) {
            float4 wv = *(const float4*)(wr + k);
            float4 xv = *(const float4*)(&z1[k]);
            acc += wv.x * xv.x + wv.y * xv.y + wv.z * xv.z + wv.w * xv.w;
        }
        z2[tid] = fmaxf(acc + b2[tid], 0.f);
    }
    __syncthreads();
    if (tid < 2) {
        const float* wr = w3 + (size_t)tid * 32;
        float acc = 0.f;
#pragma unroll
        for (int k = 0; k < 32; k++) acc += wr[k] * z2[k];
        out[(size_t)b * 2 + tid] = fmaxf(acc + b3[tid], 0.f);
    }
}

// =====================================================================
// host launcher
// =====================================================================
extern "C" void kernel_launch(void* const* d_in, const int* in_sizes, int n_in,
                              void* d_out, int out_size)
{
    const float* x    = (const float*)d_in[0];
    const float* w_ih = (const float*)d_in[1];
    const float* w_hh = (const float*)d_in[2];
    const float* b_ih = (const float*)d_in[3];
    const float* b_hh = (const float*)d_in[4];
    const float* c1w  = (const float*)d_in[5];
    const float* c1b  = (const float*)d_in[6];
    const float* c2w  = (const float*)d_in[7];
    const float* c2b  = (const float*)d_in[8];
    const float* c3w  = (const float*)d_in[9];
    const float* c3b  = (const float*)d_in[10];
    const float* c4w  = (const float*)d_in[11];
    const float* c4b  = (const float*)d_in[12];
    const float* f1w  = (const float*)d_in[13];
    const float* f1b  = (const float*)d_in[14];
    const float* f2w  = (const float*)d_in[15];
    const float* f2b  = (const float*)d_in[16];
    const float* f3w  = (const float*)d_in[17];
    const float* f3b  = (const float*)d_in[18];
    float* out = (float*)d_out;

    float *gatesx, *gates, *h, *c, *hsum, *y1, *y2, *y3, *feat;
    cudaGetSymbolAddress((void**)&gatesx, g_gatesx);
    cudaGetSymbolAddress((void**)&gates,  g_gates);
    cudaGetSymbolAddress((void**)&h,      g_h);
    cudaGetSymbolAddress((void**)&c,      g_c);
    cudaGetSymbolAddress((void**)&hsum,   g_hsum);
    cudaGetSymbolAddress((void**)&y1,     g_y1);
    cudaGetSymbolAddress((void**)&y2,     g_y2);
    cudaGetSymbolAddress((void**)&y3,     g_y3);
    cudaGetSymbolAddress((void**)&feat,   g_feat);

    const int SM1 = (32 * 137 + 64 * 224) * 4;   // 74880 B
    const int SM2 = (32 * 69 + 64 * 160) * 4;    // 49792 B
    const int SM3 = (64 * 37 + 128 * 192) * 4;   // 107776 B
    cudaFuncSetAttribute(conv1_kernel, cudaFuncAttributeMaxDynamicSharedMemorySize, SM1);
    cudaFuncSetAttribute(conv2_kernel, cudaFuncAttributeMaxDynamicSharedMemorySize, SM2);
    cudaFuncSetAttribute(conv3_kernel, cudaFuncAttributeMaxDynamicSharedMemorySize, SM3);

    // ---- CNN branch ----
    conv1_kernel<<<dim3(BB, 4), 256, SM1>>>(x, c1w, c1b, y1);
    conv2_kernel<<<BB, 256, SM2>>>(y1, c2w, c2b, y2);
    conv3_kernel<<<dim3(BB, 2), 256, SM3>>>(y2, c3w, c3b, y3);
    conv4_kernel<<<BB, 256>>>(y3, c4w, c4b, feat);

    // ---- input projection: gates_x = x @ w_ih^T + b_ih + b_hh ----
    sgemm_nt<<<dim3(G4 / 64, (BB * LL) / 64), 256>>>(
        BB * LL, G4, HH, x, HH, w_ih, HH,
        nullptr, 0, b_ih, b_hh, gatesx, G4);

    // ---- LSTM recurrence ----
    lstm_init_kernel<<<BB, 256>>>(h, c, hsum);
    for (int t = 0; t < LL; t++) {
        sgemm_nt<<<dim3(G4 / 64, BB / 64), 256>>>(
            BB, G4, LHID, h, LHID, w_hh, LHID,
            gatesx + (size_t)t * G4, LL * G4,
            nullptr, nullptr, gates, G4);
        lstm_cell_kernel<<<BB, 256>>>(gates, h, c, hsum);
    }

    // ---- MLP head ----
    mlp_kernel<<<BB, 128>>>(hsum, feat, f1w, f1b, f2w, f2b, f3w, f3b, out);
}

// round 5
// speedup vs baseline: 1.5910x; 1.5910x over previous
#include <cuda_runtime.h>
#include <math.h>

// ---------------- problem dims ----------------
#define BB   512
#define LL   128
#define HH   768
#define LHID 256
#define G4   1024   // 4*LHID

// ---------------- device scratch (no allocs allowed) ----------------
__device__ float g_gatesx[(size_t)BB * LL * G4];   // 256 MB: x @ w_ih^T + biases
__device__ float g_gates [(size_t)BB * G4];        // per-step gate buffer
__device__ float g_h     [(size_t)BB * LHID];
__device__ float g_c     [(size_t)BB * LHID];
__device__ float g_hsum  [(size_t)BB * LHID];
__device__ float g_y1    [(size_t)BB * 256 * 64];  // after conv1+pool+relu
__device__ float g_y2    [(size_t)BB * 64 * 32];   // after conv2+pool+relu
__device__ float g_y3    [(size_t)BB * 256 * 16];  // after conv3+pool+relu
__device__ float g_feat  [(size_t)BB * 256];       // after conv4+relu (flattened)

// =====================================================================
// Generic SGEMM: C[m,n] = sum_k A[m,k]*B[n,k] (+bias0[n]) (+bias1[n]) (+D[m,n])
// BM=BN=64, BK=16, 256 threads, 4x4 register tile per thread.
// =====================================================================
__global__ __launch_bounds__(256) void sgemm_nt(
    int M, int N, int K,
    const float* __restrict__ A, int lda,
    const float* __restrict__ B, int ldb,
    const float* __restrict__ D, int ldd,
    const float* __restrict__ bias0,
    const float* __restrict__ bias1,
    float* __restrict__ C, int ldc)
{
    __shared__ float As[16][64];
    __shared__ float Bs[16][64];
    const int tid = threadIdx.x;
    const int m0 = blockIdx.y * 64;
    const int n0 = blockIdx.x * 64;
    const int lr = tid >> 2;          // 0..63 : tile row for loads
    const int lc = (tid & 3) << 2;    // 0,4,8,12 : k offset for loads
    const int tx = tid & 15;
    const int ty = tid >> 4;

    float acc[4][4];
#pragma unroll
    for (int i = 0; i < 4; i++)
#pragma unroll
        for (int j = 0; j < 4; j++) acc[i][j] = 0.f;

    const float* Ap = A + (size_t)(m0 + lr) * lda + lc;
    const float* Bp = B + (size_t)(n0 + lr) * ldb + lc;

    for (int k0 = 0; k0 < K; k0 += 16) {
        float4 av = *(const float4*)(Ap + k0);
        float4 bv = *(const float4*)(Bp + k0);
        As[lc + 0][lr] = av.x; As[lc + 1][lr] = av.y;
        As[lc + 2][lr] = av.z; As[lc + 3][lr] = av.w;
        Bs[lc + 0][lr] = bv.x; Bs[lc + 1][lr] = bv.y;
        Bs[lc + 2][lr] = bv.z; Bs[lc + 3][lr] = bv.w;
        __syncthreads();
#pragma unroll
        for (int kk = 0; kk < 16; kk++) {
            float4 a = *(const float4*)&As[kk][ty << 2];
            float4 b = *(const float4*)&Bs[kk][tx << 2];
            float ar[4] = {a.x, a.y, a.z, a.w};
            float br[4] = {b.x, b.y, b.z, b.w};
#pragma unroll
            for (int i = 0; i < 4; i++)
#pragma unroll
                for (int j = 0; j < 4; j++)
                    acc[i][j] += ar[i] * br[j];
        }
        __syncthreads();
    }

#pragma unroll
    for (int i = 0; i < 4; i++) {
        int m = m0 + (ty << 2) + i;
#pragma unroll
        for (int j = 0; j < 4; j++) {
            int n = n0 + (tx << 2) + j;
            float v = acc[i][j];
            if (bias0) v += bias0[n];
            if (bias1) v += bias1[n];
            if (D)     v += D[(size_t)m * ldd + n];
            C[(size_t)m * ldc + n] = v;
        }
    }
}

// =====================================================================
// LSTM pointwise cell update (PyTorch gate order i,f,g,o)
// =====================================================================
__global__ void lstm_init_kernel(float* h, float* c, float* s)
{
    int idx = blockIdx.x * 256 + threadIdx.x;
    h[idx] = 0.f; c[idx] = 0.f; s[idx] = 0.f;
}

__device__ __forceinline__ float sigf(float x) { return 1.f / (1.f + expf(-x)); }

__global__ void lstm_cell_kernel(const float* __restrict__ gates,
                                 float* __restrict__ h,
                                 float* __restrict__ c,
                                 float* __restrict__ hsum)
{
    int idx = blockIdx.x * 256 + threadIdx.x;      // 512*256
    int b = idx >> 8, j = idx & 255;
    const float* g = gates + (size_t)b * G4;
    float si = sigf(g[j]);
    float sf = sigf(g[256 + j]);
    float tg = tanhf(g[512 + j]);
    float so = sigf(g[768 + j]);
    float cn = sf * c[idx] + si * tg;
    c[idx] = cn;
    float hn = so * tanhf(cn);
    h[idx] = hn;
    hsum[idx] += hn;
}

// =====================================================================
// conv1: x[B,128,768] -> conv(k=7,pad=3,Cout=256) + bias -> pool2 -> relu
// out y1[B,256,64].  Block = (b, co-group of 64). 256 thr.
// smem: xs[32 ci][137 pitch, 134 used], ws[64 co][224 = 32ci*7kw]
// thread: lane covers conv pos {lane+32i}, cog=tid>>5 covers co {cog+8j}
// pooling of adjacent positions via shfl_xor(.,1).
// =====================================================================
__global__ __launch_bounds__(256) void conv1_kernel(
    const float* __restrict__ x, const float* __restrict__ w,
    const float* __restrict__ bias, float* __restrict__ out)
{
    extern __shared__ float sm[];
    float* xs = sm;             // 32*137
    float* ws = sm + 32 * 137;  // 64*224
    const int b   = blockIdx.x;
    const int co0 = blockIdx.y * 64;
    const int tid = threadIdx.x;
    const int lane = tid & 31;
    const int cog  = tid >> 5;  // 0..7

    float acc[8][4];
#pragma unroll
    for (int j = 0; j < 8; j++)
#pragma unroll
        for (int i = 0; i < 4; i++) acc[j][i] = 0.f;

    const float* xb = x + (size_t)b * LL * HH;

    for (int ci0 = 0; ci0 < HH; ci0 += 32) {
        // stage x window (seq pos -3..130 -> s=0..133), coalesced over ci
        for (int idx = tid; idx < 32 * 134; idx += 256) {
            int cil = idx & 31, s = idx >> 5;
            int p = s - 3;
            xs[cil * 137 + s] =
                (p >= 0 && p < LL) ? xb[(size_t)p * HH + ci0 + cil] : 0.f;
        }
        // stage weights: ws[col][r], r = cil*7+kw (contiguous in gmem per col)
        for (int idx = tid; idx < 64 * 224; idx += 256) {
            int col = idx / 224, r = idx - col * 224;
            ws[idx] = w[(size_t)(co0 + col) * (HH * 7) + ci0 * 7 + r];
        }
        __syncthreads();

        for (int ci = 0; ci < 32; ci++) {
            const float* xr = &xs[ci * 137 + lane];
            const float* wr = &ws[cog * 224 + ci * 7];
#pragma unroll
            for (int kw = 0; kw < 7; kw++) {
                float xv0 = xr[kw];
                float xv1 = xr[kw + 32];
                float xv2 = xr[kw + 64];
                float xv3 = xr[kw + 96];
#pragma unroll
                for (int j = 0; j < 8; j++) {
                    float wv = wr[j * (8 * 224) + kw];  // ws[cog+8j][ci*7+kw]
                    acc[j][0] += wv * xv0;
                    acc[j][1] += wv * xv1;
                    acc[j][2] += wv * xv2;
                    acc[j][3] += wv * xv3;
                }
            }
        }
        __syncthreads();
    }

#pragma unroll
    for (int j = 0; j < 8; j++) {
        int co = co0 + cog + 8 * j;
        float bv = bias[co];
#pragma unroll
        for (int i = 0; i < 4; i++) {
            float v = acc[j][i] + bv;
            float o = __shfl_xor_sync(0xffffffffu, v, 1);
            float m = fmaxf(v, o);
            if (!(lane & 1)) {
                int q = (lane >> 1) + 16 * i;        // pooled position 0..63
                out[(size_t)b * 256 * 64 + (size_t)co * 64 + q] = fmaxf(m, 0.f);
            }
        }
    }
}

// =====================================================================
// conv2: y1[B,256,64] -> conv(k=5,pad=2,Cout=64)+bias -> pool2 -> relu
// out y2[B,64,32]. Block per b. smem: xs[32][69], ws[64][160].
// =====================================================================
__global__ __launch_bounds__(256) void conv2_kernel(
    const float* __restrict__ in, const float* __restrict__ w,
    const float* __restrict__ bias, float* __restrict__ out)
{
    extern __shared__ float sm[];
    float* xs = sm;            // 32*69
    float* ws = sm + 32 * 69;  // 64*160
    const int b = blockIdx.x;
    const int tid = threadIdx.x;
    const int lane = tid & 31;
    const int cog  = tid >> 5;  // co = cog + 8j, j 0..7

    float acc[8][2];
#pragma unroll
    for (int j = 0; j < 8; j++) { acc[j][0] = 0.f; acc[j][1] = 0.f; }

    const float* ib = in + (size_t)b * 256 * 64;

    for (int ci0 = 0; ci0 < 256; ci0 += 32) {
        for (int idx = tid; idx < 32 * 68; idx += 256) {
            int cil = idx / 68, s = idx - cil * 68;
            int p = s - 2;
            xs[cil * 69 + s] =
                (p >= 0 && p < 64) ? ib[(size_t)(ci0 + cil) * 64 + p] : 0.f;
        }
        for (int idx = tid; idx < 64 * 160; idx += 256) {
            int col = idx / 160, r = idx - col * 160;
            ws[idx] = w[(size_t)col * (256 * 5) + ci0 * 5 + r];
        }
        __syncthreads();

        for (int ci = 0; ci < 32; ci++) {
            const float* xr = &xs[ci * 69 + lane];
            const float* wr = &ws[cog * 160 + ci * 5];
#pragma unroll
            for (int kw = 0; kw < 5; kw++) {
                float xv0 = xr[kw];
                float xv1 = xr[kw + 32];
#pragma unroll
                for (int j = 0; j < 8; j++) {
                    float wv = wr[j * (8 * 160) + kw];
                    acc[j][0] += wv * xv0;
                    acc[j][1] += wv * xv1;
                }
            }
        }
        __syncthreads();
    }

#pragma unroll
    for (int j = 0; j < 8; j++) {
        int co = cog + 8 * j;
        float bv = bias[co];
#pragma unroll
        for (int i = 0; i < 2; i++) {
            float v = acc[j][i] + bv;
            float o = __shfl_xor_sync(0xffffffffu, v, 1);
            float m = fmaxf(v, o);
            if (!(lane & 1)) {
                int q = (lane >> 1) + 16 * i;   // 0..31
                out[(size_t)b * 64 * 32 + (size_t)co * 32 + q] = fmaxf(m, 0.f);
            }
        }
    }
}

// =====================================================================
// conv3: y2[B,64,32] -> conv(k=3,pad=1,Cout=256)+bias -> pool2 -> relu
// out y3[B,256,16]. Block = (b, co-group of 128). smem: xs[64][37], ws[128][192]
// =====================================================================
__global__ __launch_bounds__(256) void conv3_kernel(
    const float* __restrict__ in, const float* __restrict__ w,
    const float* __restrict__ bias, float* __restrict__ out)
{
    extern __shared__ float sm[];
    float* xs = sm;            // 64*37 (34 used)
    float* ws = sm + 64 * 37;  // 128*192
    const int b   = blockIdx.x;
    const int co0 = blockIdx.y * 128;
    const int tid = threadIdx.x;
    const int lane = tid & 31;      // conv position 0..31
    const int cog  = tid >> 5;      // co = co0 + cog + 8j, j 0..15

    float acc[16];
#pragma unroll
    for (int j = 0; j < 16; j++) acc[j] = 0.f;

    const float* ib = in + (size_t)b * 64 * 32;

    for (int idx = tid; idx < 64 * 34; idx += 256) {
        int cil = idx / 34, s = idx - cil * 34;
        int p = s - 1;
        xs[cil * 37 + s] = (p >= 0 && p < 32) ? ib[(size_t)cil * 32 + p] : 0.f;
    }
    for (int idx = tid; idx < 128 * 192; idx += 256) {
        int col = idx / 192, r = idx - col * 192;
        ws[idx] = w[(size_t)(co0 + col) * 192 + r];
    }
    __syncthreads();

    for (int ci = 0; ci < 64; ci++) {
        const float* xr = &xs[ci * 37 + lane];
        float xv0 = xr[0], xv1 = xr[1], xv2 = xr[2];
        const float* wr = &ws[cog * 192 + ci * 3];
#pragma unroll
        for (int j = 0; j < 16; j++) {
            const float* wj = wr + j * (8 * 192);
            acc[j] += wj[0] * xv0 + wj[1] * xv1 + wj[2] * xv2;
        }
    }

#pragma unroll
    for (int j = 0; j < 16; j++) {
        int co = co0 + cog + 8 * j;
        float v = acc[j] + bias[co];
        float o = __shfl_xor_sync(0xffffffffu, v, 1);
        float m = fmaxf(v, o);
        if (!(lane & 1)) {
            int q = lane >> 1;   // 0..15
            out[(size_t)b * 256 * 16 + (size_t)co * 16 + q] = fmaxf(m, 0.f);
        }
    }
}

// =====================================================================
// conv4 (k=1, 256->16) + relu + flatten: feat[b, co*16 + pos]
// =====================================================================
__global__ __launch_bounds__(256) void conv4_kernel(
    const float* __restrict__ in, const float* __restrict__ w,
    const float* __restrict__ bias, float* __restrict__ out)
{
    __shared__ float xsh[4096];
    __shared__ float wsh[4096];
    int b = blockIdx.x, tid = threadIdx.x;
    const float* ib = in + (size_t)b * 4096;
    for (int i = tid; i < 4096; i += 256) { xsh[i] = ib[i]; wsh[i] = w[i]; }
    __syncthreads();
    int co = tid >> 4, p = tid & 15;
    float acc = bias[co];
#pragma unroll 8
    for (int ci = 0; ci < 256; ci++)
        acc += xsh[ci * 16 + p] * wsh[co * 256 + ci];
    out[(size_t)b * 256 + co * 16 + p] = fmaxf(acc, 0.f);
}

// =====================================================================
// MLP head: zin = [hsum/128 , feat] ; fc1(512->128) relu; fc2(128->32) relu;
// fc3(32->2) relu. One block per batch row.
// =====================================================================
__global__ __launch_bounds__(128) void mlp_kernel(
    const float* __restrict__ hsum, const float* __restrict__ feat,
    const float* __restrict__ w1, const float* __restrict__ b1,
    const float* __restrict__ w2, const float* __restrict__ b2,
    const float* __restrict__ w3, const float* __restrict__ b3,
    float* __restrict__ out)
{
    __shared__ float zin[512];
    __shared__ float z1[128];
    __shared__ float z2[32];
    int b = blockIdx.x, tid = threadIdx.x;
    for (int i = tid; i < 256; i += 128) {
        zin[i]       = hsum[(size_t)b * 256 + i] * (1.f / 128.f);
        zin[256 + i] = feat[(size_t)b * 256 + i];
    }
    __syncthreads();
    {
        const float* wr = w1 + (size_t)tid * 512;
        float acc = 0.f;
#pragma unroll 4
        for (int k = 0; k < 512; k += 4) {
            float4 wv = *(const float4*)(wr + k);
            float4 xv = *(const float4*)(&zin[k]);
            acc += wv.x * xv.x + wv.y * xv.y + wv.z * xv.z + wv.w * xv.w;
        }
        z1[tid] = fmaxf(acc + b1[tid], 0.f);
    }
    __syncthreads();
    if (tid < 32) {
        const float* wr = w2 + (size_t)tid * 128;
        float acc = 0.f;
#pragma unroll
        for (int k = 0; k < 128; k += 4) {
            float4 wv = *(const float4*)(wr + k);
            float4 xv = *(const float4*)(&z1[k]);
            acc += wv.x * xv.x + wv.y * xv.y + wv.z * xv.z + wv.w * xv.w;
        }
        z2[tid] = fmaxf(acc + b2[tid], 0.f);
    }
    __syncthreads();
    if (tid < 2) {
        const float* wr = w3 + (size_t)tid * 32;
        float acc = 0.f;
#pragma unroll
        for (int k = 0; k < 32; k++) acc += wr[k] * z2[k];
        out[(size_t)b * 2 + tid] = fmaxf(acc + b3[tid], 0.f);
    }
}

// =====================================================================
// host launcher
// =====================================================================
extern "C" void kernel_launch(void* const* d_in, const int* in_sizes, int n_in,
                              void* d_out, int out_size)
{
    const float* x    = (const float*)d_in[0];
    const float* w_ih = (const float*)d_in[1];
    const float* w_hh = (const float*)d_in[2];
    const float* b_ih = (const float*)d_in[3];
    const float* b_hh = (const float*)d_in[4];
    const float* c1w  = (const float*)d_in[5];
    const float* c1b  = (const float*)d_in[6];
    const float* c2w  = (const float*)d_in[7];
    const float* c2b  = (const float*)d_in[8];
    const float* c3w  = (const float*)d_in[9];
    const float* c3b  = (const float*)d_in[10];
    const float* c4w  = (const float*)d_in[11];
    const float* c4b  = (const float*)d_in[12];
    const float* f1w  = (const float*)d_in[13];
    const float* f1b  = (const float*)d_in[14];
    const float* f2w  = (const float*)d_in[15];
    const float* f2b  = (const float*)d_in[16];
    const float* f3w  = (const float*)d_in[17];
    const float* f3b  = (const float*)d_in[18];
    float* out = (float*)d_out;

    float *gatesx, *gates, *h, *c, *hsum, *y1, *y2, *y3, *feat;
    cudaGetSymbolAddress((void**)&gatesx, g_gatesx);
    cudaGetSymbolAddress((void**)&gates,  g_gates);
    cudaGetSymbolAddress((void**)&h,      g_h);
    cudaGetSymbolAddress((void**)&c,      g_c);
    cudaGetSymbolAddress((void**)&hsum,   g_hsum);
    cudaGetSymbolAddress((void**)&y1,     g_y1);
    cudaGetSymbolAddress((void**)&y2,     g_y2);
    cudaGetSymbolAddress((void**)&y3,     g_y3);
    cudaGetSymbolAddress((void**)&feat,   g_feat);

    const int SM1 = (32 * 137 + 64 * 224) * 4;   // 74880 B
    const int SM2 = (32 * 69 + 64 * 160) * 4;    // 49792 B
    const int SM3 = (64 * 37 + 128 * 192) * 4;   // 107776 B
    cudaFuncSetAttribute(conv1_kernel, cudaFuncAttributeMaxDynamicSharedMemorySize, SM1);
    cudaFuncSetAttribute(conv2_kernel, cudaFuncAttributeMaxDynamicSharedMemorySize, SM2);
    cudaFuncSetAttribute(conv3_kernel, cudaFuncAttributeMaxDynamicSharedMemorySize, SM3);

    // ---- CNN branch ----
    conv1_kernel<<<dim3(BB, 4), 256, SM1>>>(x, c1w, c1b, y1);
    conv2_kernel<<<BB, 256, SM2>>>(y1, c2w, c2b, y2);
    conv3_kernel<<<dim3(BB, 2), 256, SM3>>>(y2, c3w, c3b, y3);
    conv4_kernel<<<BB, 256>>>(y3, c4w, c4b, feat);

    // ---- input projection: gates_x = x @ w_ih^T + b_ih + b_hh ----
    sgemm_nt<<<dim3(G4 / 64, (BB * LL) / 64), 256>>>(
        BB * LL, G4, HH, x, HH, w_ih, HH,
        nullptr, 0, b_ih, b_hh, gatesx, G4);

    // ---- LSTM recurrence ----
    lstm_init_kernel<<<BB, 256>>>(h, c, hsum);
    for (int t = 0; t < LL; t++) {
        sgemm_nt<<<dim3(G4 / 64, BB / 64), 256>>>(
            BB, G4, LHID, h, LHID, w_hh, LHID,
            gatesx + (size_t)t * G4, LL * G4,
            nullptr, nullptr, gates, G4);
        lstm_cell_kernel<<<BB, 256>>>(gates, h, c, hsum);
    }

    // ---- MLP head ----
    mlp_kernel<<<BB, 128>>>(hsum, feat, f1w, f1b, f2w, f2b, f3w, f3b, out);
}

// round 6
// speedup vs baseline: 1.7000x; 1.0685x over previous
#include <cuda_runtime.h>
#include <math.h>

// ---------------- problem dims ----------------
#define BB   512
#define LL   128
#define HH   768
#define LHID 256
#define G4   1024   // 4*LHID

typedef unsigned long long ull;

// ---------------- device scratch (no allocs allowed) ----------------
__device__ float g_gatesx[(size_t)BB * LL * G4];   // 256 MB: x @ w_ih^T + biases
__device__ float g_hA    [(size_t)BB * LHID];
__device__ float g_hB    [(size_t)BB * LHID];
__device__ float g_c     [(size_t)BB * LHID];
__device__ float g_hsum  [(size_t)BB * LHID];
__device__ float g_y1    [(size_t)BB * 256 * 64];
__device__ float g_y2    [(size_t)BB * 64 * 32];
__device__ float g_y3    [(size_t)BB * 256 * 16];
__device__ float g_feat  [(size_t)BB * 256];

// ---------------- f32x2 helpers ----------------
__device__ __forceinline__ ull pack2(float lo, float hi) {
    ull r; asm("mov.b64 %0, {%1, %2};" : "=l"(r) : "f"(lo), "f"(hi)); return r;
}
__device__ __forceinline__ ull bcast2(float v) { return pack2(v, v); }
__device__ __forceinline__ void fma2(ull& d, ull a, ull b) {
    asm("fma.rn.f32x2 %0, %1, %2, %0;" : "+l"(d) : "l"(a), "l"(b));
}
__device__ __forceinline__ float2 unpack2(ull v) {
    float2 r; asm("mov.b64 {%0, %1}, %2;" : "=f"(r.x), "=f"(r.y) : "l"(v)); return r;
}
__device__ __forceinline__ float sigf(float x) { return 1.f / (1.f + expf(-x)); }

// =====================================================================
// xproj: C[M=BB*LL, N=1024] = x @ w_ih^T + b_ih + b_hh   (FFMA2 GEMM)
// BM=128, BN=128, BK=16, 256 threads, 8m x 8n per thread, pairs over m.
// =====================================================================
#define PA 132
__global__ __launch_bounds__(256) void xproj_kernel(
    const float* __restrict__ A, const float* __restrict__ Bw,
    const float* __restrict__ bias0, const float* __restrict__ bias1,
    float* __restrict__ C)
{
    __shared__ __align__(16) float As[16 * PA];  // [k][m]
    __shared__ __align__(16) float Bs[16 * PA];  // [k][n]
    const int tid = threadIdx.x;
    const int m0 = blockIdx.y * 128;
    const int n0 = blockIdx.x * 128;
    const int tx = tid & 15;      // n: tx*8 .. +7
    const int ty = tid >> 4;      // m: ty*8 .. +7

    ull acc[4][8];                // [mpair][n]
#pragma unroll
    for (int i = 0; i < 4; i++)
#pragma unroll
        for (int j = 0; j < 8; j++) acc[i][j] = 0ULL;

    const int rr  = tid >> 2;        // 0..63
    const int cc4 = (tid & 3) << 2;  // 0,4,8,12
    const float* Ap = A  + (size_t)(m0 + rr) * HH + cc4;
    const float* Bp = Bw + (size_t)(n0 + rr) * HH + cc4;

    float4 ra0 = *(const float4*)Ap;
    float4 ra1 = *(const float4*)(Ap + (size_t)64 * HH);
    float4 rb0 = *(const float4*)Bp;
    float4 rb1 = *(const float4*)(Bp + (size_t)64 * HH);

    for (int ch = 0; ch < 48; ch++) {
        const float* pa0 = (const float*)&ra0;
        const float* pa1 = (const float*)&ra1;
        const float* pb0 = (const float*)&rb0;
        const float* pb1 = (const float*)&rb1;
#pragma unroll
        for (int i = 0; i < 4; i++) {
            As[(cc4 + i) * PA + rr]      = pa0[i];
            As[(cc4 + i) * PA + rr + 64] = pa1[i];
            Bs[(cc4 + i) * PA + rr]      = pb0[i];
            Bs[(cc4 + i) * PA + rr + 64] = pb1[i];
        }
        __syncthreads();
        if (ch < 47) {
            Ap += 16; Bp += 16;
            ra0 = *(const float4*)Ap;
            ra1 = *(const float4*)(Ap + (size_t)64 * HH);
            rb0 = *(const float4*)Bp;
            rb1 = *(const float4*)(Bp + (size_t)64 * HH);
        }
#pragma unroll
        for (int kk = 0; kk < 16; kk++) {
            ulonglong2 aA = *(const ulonglong2*)&As[kk * PA + ty * 8];      // m pairs 0,1
            ulonglong2 aB = *(const ulonglong2*)&As[kk * PA + ty * 8 + 4];  // m pairs 2,3
            float4 b0 = *(const float4*)&Bs[kk * PA + tx * 8];
            float4 b1 = *(const float4*)&Bs[kk * PA + tx * 8 + 4];
            ull bb[8];
            bb[0] = bcast2(b0.x); bb[1] = bcast2(b0.y);
            bb[2] = bcast2(b0.z); bb[3] = bcast2(b0.w);
            bb[4] = bcast2(b1.x); bb[5] = bcast2(b1.y);
            bb[6] = bcast2(b1.z); bb[7] = bcast2(b1.w);
#pragma unroll
            for (int j = 0; j < 8; j++) {
                fma2(acc[0][j], aA.x, bb[j]);
                fma2(acc[1][j], aA.y, bb[j]);
                fma2(acc[2][j], aB.x, bb[j]);
                fma2(acc[3][j], aB.y, bb[j]);
            }
        }
        __syncthreads();
    }

    // epilogue: add biases, store as float4s
    float bs[8];
#pragma unroll
    for (int j = 0; j < 8; j++) {
        int n = n0 + tx * 8 + j;
        bs[j] = bias0[n] + bias1[n];
    }
#pragma unroll
    for (int mp = 0; mp < 4; mp++) {
        float2 v[8];
#pragma unroll
        for (int j = 0; j < 8; j++) v[j] = unpack2(acc[mp][j]);
        int mlo = m0 + ty * 8 + mp * 2;
        float* r0 = C + (size_t)mlo * G4 + n0 + tx * 8;
        float* r1 = r0 + G4;
        float4 o;
        o.x = v[0].x + bs[0]; o.y = v[1].x + bs[1]; o.z = v[2].x + bs[2]; o.w = v[3].x + bs[3];
        *(float4*)r0 = o;
        o.x = v[4].x + bs[4]; o.y = v[5].x + bs[5]; o.z = v[6].x + bs[6]; o.w = v[7].x + bs[7];
        *(float4*)(r0 + 4) = o;
        o.x = v[0].y + bs[0]; o.y = v[1].y + bs[1]; o.z = v[2].y + bs[2]; o.w = v[3].y + bs[3];
        *(float4*)r1 = o;
        o.x = v[4].y + bs[4]; o.y = v[5].y + bs[5]; o.z = v[6].y + bs[6]; o.w = v[7].y + bs[7];
        *(float4*)(r1 + 4) = o;
    }
}

// =====================================================================
// Fused LSTM step: gates = hprev @ w_hh^T (+gatesx[:,t,:]) -> cell update.
// Block: 64 b x 16 j (owns all 4 gates for its j's). Grid (16, 8).
// 256 thr, thread = 4 b (2 pairs) x 1 j x 4 gates. K=256, BK=32.
// =====================================================================
__global__ __launch_bounds__(256) void lstm_step_kernel(
    const float* __restrict__ hprev, float* __restrict__ hnext,
    float* __restrict__ c, float* __restrict__ hsum,
    const float* __restrict__ whh, const float* __restrict__ gx, int t)
{
    __shared__ __align__(16) float As[32 * 68];  // [k][b]  64 b
    __shared__ __align__(16) float Bs[32 * 68];  // [k][n]  n = gate*16 + jj
    const int tid = threadIdx.x;
    const int j0 = blockIdx.x * 16;
    const int b0 = blockIdx.y * 64;
    const int tx = tid & 15;   // j = j0 + tx
    const int ty = tid >> 4;   // b = b0 + ty*4 .. +3

    ull acc[2][4];             // [bpair][gate]
#pragma unroll
    for (int i = 0; i < 2; i++)
#pragma unroll
        for (int g = 0; g < 4; g++) acc[i][g] = 0ULL;

    for (int k0 = 0; k0 < LHID; k0 += 32) {
        for (int idx = tid; idx < 64 * 32; idx += 256) {
            int bb = idx >> 5, k = idx & 31;
            As[k * 68 + bb] = hprev[(size_t)(b0 + bb) * LHID + k0 + k];
        }
        for (int idx = tid; idx < 64 * 32; idx += 256) {
            int n = idx >> 5, k = idx & 31;
            int grow = (n >> 4) * LHID + j0 + (n & 15);
            Bs[k * 68 + n] = whh[(size_t)grow * LHID + k0 + k];
        }
        __syncthreads();
#pragma unroll
        for (int kk = 0; kk < 32; kk++) {
            ulonglong2 ap = *(const ulonglong2*)&As[kk * 68 + ty * 4];
            ull p0 = bcast2(Bs[kk * 68 + tx]);
            ull p1 = bcast2(Bs[kk * 68 + 16 + tx]);
            ull p2 = bcast2(Bs[kk * 68 + 32 + tx]);
            ull p3 = bcast2(Bs[kk * 68 + 48 + tx]);
            fma2(acc[0][0], ap.x, p0); fma2(acc[1][0], ap.y, p0);
            fma2(acc[0][1], ap.x, p1); fma2(acc[1][1], ap.y, p1);
            fma2(acc[0][2], ap.x, p2); fma2(acc[1][2], ap.y, p2);
            fma2(acc[0][3], ap.x, p3); fma2(acc[1][3], ap.y, p3);
        }
        __syncthreads();
    }

    const int j = j0 + tx;
#pragma unroll
    for (int bp = 0; bp < 2; bp++) {
        float2 vi = unpack2(acc[bp][0]);
        float2 vf = unpack2(acc[bp][1]);
        float2 vg = unpack2(acc[bp][2]);
        float2 vo = unpack2(acc[bp][3]);
#pragma unroll
        for (int hf = 0; hf < 2; hf++) {
            int b = b0 + ty * 4 + bp * 2 + hf;
            float gi = hf ? vi.y : vi.x;
            float gf = hf ? vf.y : vf.x;
            float gg = hf ? vg.y : vg.x;
            float go = hf ? vo.y : vo.x;
            size_t gxo = ((size_t)b * LL + t) * G4 + j;
            float i_ = sigf(gi + gx[gxo]);
            float f_ = sigf(gf + gx[gxo + 256]);
            float g_ = tanhf(gg + gx[gxo + 512]);
            float o_ = sigf(go + gx[gxo + 768]);
            int ci = b * LHID + j;
            float cn = f_ * c[ci] + i_ * g_;
            c[ci] = cn;
            float hn = o_ * tanhf(cn);
            hnext[ci] = hn;
            hsum[ci] += hn;
        }
    }
}

__global__ void lstm_init_kernel(float* h, float* c, float* s)
{
    int idx = blockIdx.x * 256 + threadIdx.x;
    h[idx] = 0.f; c[idx] = 0.f; s[idx] = 0.f;
}

// =====================================================================
// conv1 (FFMA2): x[B,128,768] -> conv(k=7,pad=3,Cout=256)+bias -> pool2 -> relu
// Block (b, half of co: 128). 256 thr: lane -> pos {lane+32i}, cog=tid>>5 ->
// 16 contiguous co (8 pairs). ci chunk = 16.
// smem: xs[16][137], wsT[112 r][132 pitch] (r = ci*7+kw, col = co local).
// =====================================================================
#define W1PITCH 132
__global__ __launch_bounds__(256) void conv1_kernel(
    const float* __restrict__ x, const float* __restrict__ w,
    const float* __restrict__ bias, float* __restrict__ out)
{
    extern __shared__ __align__(16) float sm[];
    float* xs  = sm;              // 16*137 = 2192 floats
    float* wsT = sm + 16 * 137;   // 112*132 floats
    const int b   = blockIdx.x;
    const int cb0 = blockIdx.y * 128;   // co base of this block
    const int tid = threadIdx.x;
    const int lane = tid & 31;
    const int cog  = tid >> 5;          // co local: cog*16 .. +15

    ull acc[8][4];   // [copair][pos]
#pragma unroll
    for (int q = 0; q < 8; q++)
#pragma unroll
        for (int i = 0; i < 4; i++) acc[q][i] = 0ULL;

    const float* xb = x + (size_t)b * LL * HH;

    for (int ci0 = 0; ci0 < HH; ci0 += 16) {
        // stage x window: seq pos -3..130 -> s 0..133
        for (int idx = tid; idx < 16 * 134; idx += 256) {
            int cil = idx & 15, s = idx >> 4;
            int p = s - 3;
            xs[cil * 137 + s] =
                (p >= 0 && p < LL) ? xb[(size_t)p * HH + ci0 + cil] : 0.f;
        }
        // stage weights transposed: wsT[r][col], r = cil*7+kw (0..111)
        for (int idx = tid; idx < 112 * 128; idx += 256) {
            int col = idx / 112, r = idx - col * 112;
            wsT[r * W1PITCH + col] = w[(size_t)(cb0 + col) * (HH * 7) + ci0 * 7 + r];
        }
        __syncthreads();

        for (int cil = 0; cil < 16; cil++) {
            const float* xr = &xs[cil * 137 + lane];
            const int r0 = cil * 7;
#pragma unroll
            for (int kw = 0; kw < 7; kw++) {
                ull xb0 = bcast2(xr[kw]);
                ull xb1 = bcast2(xr[kw + 32]);
                ull xb2 = bcast2(xr[kw + 64]);
                ull xb3 = bcast2(xr[kw + 96]);
                const float* wrow = &wsT[(r0 + kw) * W1PITCH + cog * 16];
                ulonglong2 wA = *(const ulonglong2*)(wrow);       // pairs 0,1
                ulonglong2 wB = *(const ulonglong2*)(wrow + 4);   // pairs 2,3
                ulonglong2 wC = *(const ulonglong2*)(wrow + 8);   // pairs 4,5
                ulonglong2 wD = *(const ulonglong2*)(wrow + 12);  // pairs 6,7
                fma2(acc[0][0], wA.x, xb0); fma2(acc[0][1], wA.x, xb1);
                fma2(acc[0][2], wA.x, xb2); fma2(acc[0][3], wA.x, xb3);
                fma2(acc[1][0], wA.y, xb0); fma2(acc[1][1], wA.y, xb1);
                fma2(acc[1][2], wA.y, xb2); fma2(acc[1][3], wA.y, xb3);
                fma2(acc[2][0], wB.x, xb0); fma2(acc[2][1], wB.x, xb1);
                fma2(acc[2][2], wB.x, xb2); fma2(acc[2][3], wB.x, xb3);
                fma2(acc[3][0], wB.y, xb0); fma2(acc[3][1], wB.y, xb1);
                fma2(acc[3][2], wB.y, xb2); fma2(acc[3][3], wB.y, xb3);
                fma2(acc[4][0], wC.x, xb0); fma2(acc[4][1], wC.x, xb1);
                fma2(acc[4][2], wC.x, xb2); fma2(acc[4][3], wC.x, xb3);
                fma2(acc[5][0], wC.y, xb0); fma2(acc[5][1], wC.y, xb1);
                fma2(acc[5][2], wC.y, xb2); fma2(acc[5][3], wC.y, xb3);
                fma2(acc[6][0], wD.x, xb0); fma2(acc[6][1], wD.x, xb1);
                fma2(acc[6][2], wD.x, xb2); fma2(acc[6][3], wD.x, xb3);
                fma2(acc[7][0], wD.y, xb0); fma2(acc[7][1], wD.y, xb1);
                fma2(acc[7][2], wD.y, xb2); fma2(acc[7][3], wD.y, xb3);
            }
        }
        __syncthreads();
    }

    // epilogue: bias + pool2 (adjacent lanes) + relu
#pragma unroll
    for (int q = 0; q < 8; q++) {
        int co = cb0 + cog * 16 + 2 * q;
        float bv0 = bias[co], bv1 = bias[co + 1];
#pragma unroll
        for (int i = 0; i < 4; i++) {
            float2 v = unpack2(acc[q][i]);
            float a0 = v.x + bv0;
            float a1 = v.y + bv1;
            float m0 = fmaxf(a0, __shfl_xor_sync(0xffffffffu, a0, 1));
            float m1 = fmaxf(a1, __shfl_xor_sync(0xffffffffu, a1, 1));
            if (!(lane & 1)) {
                int qq = (lane >> 1) + 16 * i;
                out[(size_t)b * 256 * 64 + (size_t)co * 64 + qq]       = fmaxf(m0, 0.f);
                out[(size_t)b * 256 * 64 + (size_t)(co + 1) * 64 + qq] = fmaxf(m1, 0.f);
            }
        }
    }
}

// =====================================================================
// conv2: y1[B,256,64] -> conv(k=5,pad=2,Cout=64)+bias -> pool2 -> relu
// =====================================================================
__global__ __launch_bounds__(256) void conv2_kernel(
    const float* __restrict__ in, const float* __restrict__ w,
    const float* __restrict__ bias, float* __restrict__ out)
{
    extern __shared__ float sm[];
    float* xs = sm;            // 32*69
    float* ws = sm + 32 * 69;  // 64*160
    const int b = blockIdx.x;
    const int tid = threadIdx.x;
    const int lane = tid & 31;
    const int cog  = tid >> 5;

    float acc[8][2];
#pragma unroll
    for (int j = 0; j < 8; j++) { acc[j][0] = 0.f; acc[j][1] = 0.f; }

    const float* ib = in + (size_t)b * 256 * 64;

    for (int ci0 = 0; ci0 < 256; ci0 += 32) {
        for (int idx = tid; idx < 32 * 68; idx += 256) {
            int cil = idx / 68, s = idx - cil * 68;
            int p = s - 2;
            xs[cil * 69 + s] =
                (p >= 0 && p < 64) ? ib[(size_t)(ci0 + cil) * 64 + p] : 0.f;
        }
        for (int idx = tid; idx < 64 * 160; idx += 256) {
            int col = idx / 160, r = idx - col * 160;
            ws[idx] = w[(size_t)col * (256 * 5) + ci0 * 5 + r];
        }
        __syncthreads();

        for (int ci = 0; ci < 32; ci++) {
            const float* xr = &xs[ci * 69 + lane];
            const float* wr = &ws[cog * 160 + ci * 5];
#pragma unroll
            for (int kw = 0; kw < 5; kw++) {
                float xv0 = xr[kw];
                float xv1 = xr[kw + 32];
#pragma unroll
                for (int j = 0; j < 8; j++) {
                    float wv = wr[j * (8 * 160) + kw];
                    acc[j][0] += wv * xv0;
                    acc[j][1] += wv * xv1;
                }
            }
        }
        __syncthreads();
    }

#pragma unroll
    for (int j = 0; j < 8; j++) {
        int co = cog + 8 * j;
        float bv = bias[co];
#pragma unroll
        for (int i = 0; i < 2; i++) {
            float v = acc[j][i] + bv;
            float o = __shfl_xor_sync(0xffffffffu, v, 1);
            float m = fmaxf(v, o);
            if (!(lane & 1)) {
                int q = (lane >> 1) + 16 * i;
                out[(size_t)b * 64 * 32 + (size_t)co * 32 + q] = fmaxf(m, 0.f);
            }
        }
    }
}

// =====================================================================
// conv3: y2[B,64,32] -> conv(k=3,pad=1,Cout=256)+bias -> pool2 -> relu
// =====================================================================
__global__ __launch_bounds__(256) void conv3_kernel(
    const float* __restrict__ in, const float* __restrict__ w,
    const float* __restrict__ bias, float* __restrict__ out)
{
    extern __shared__ float sm[];
    float* xs = sm;            // 64*37
    float* ws = sm + 64 * 37;  // 128*192
    const int b   = blockIdx.x;
    const int co0 = blockIdx.y * 128;
    const int tid = threadIdx.x;
    const int lane = tid & 31;
    const int cog  = tid >> 5;

    float acc[16];
#pragma unroll
    for (int j = 0; j < 16; j++) acc[j] = 0.f;

    const float* ib = in + (size_t)b * 64 * 32;

    for (int idx = tid; idx < 64 * 34; idx += 256) {
        int cil = idx / 34, s = idx - cil * 34;
        int p = s - 1;
        xs[cil * 37 + s] = (p >= 0 && p < 32) ? ib[(size_t)cil * 32 + p] : 0.f;
    }
    for (int idx = tid; idx < 128 * 192; idx += 256) {
        int col = idx / 192, r = idx - col * 192;
        ws[idx] = w[(size_t)(co0 + col) * 192 + r];
    }
    __syncthreads();

    for (int ci = 0; ci < 64; ci++) {
        const float* xr = &xs[ci * 37 + lane];
        float xv0 = xr[0], xv1 = xr[1], xv2 = xr[2];
        const float* wr = &ws[cog * 192 + ci * 3];
#pragma unroll
        for (int j = 0; j < 16; j++) {
            const float* wj = wr + j * (8 * 192);
            acc[j] += wj[0] * xv0 + wj[1] * xv1 + wj[2] * xv2;
        }
    }

#pragma unroll
    for (int j = 0; j < 16; j++) {
        int co = co0 + cog + 8 * j;
        float v = acc[j] + bias[co];
        float o = __shfl_xor_sync(0xffffffffu, v, 1);
        float m = fmaxf(v, o);
        if (!(lane & 1)) {
            int q = lane >> 1;
            out[(size_t)b * 256 * 16 + (size_t)co * 16 + q] = fmaxf(m, 0.f);
        }
    }
}

// =====================================================================
// conv4 (k=1, 256->16) + relu + flatten
// =====================================================================
__global__ __launch_bounds__(256) void conv4_kernel(
    const float* __restrict__ in, const float* __restrict__ w,
    const float* __restrict__ bias, float* __restrict__ out)
{
    __shared__ float xsh[4096];
    __shared__ float wsh[4096];
    int b = blockIdx.x, tid = threadIdx.x;
    const float* ib = in + (size_t)b * 4096;
    for (int i = tid; i < 4096; i += 256) { xsh[i] = ib[i]; wsh[i] = w[i]; }
    __syncthreads();
    int co = tid >> 4, p = tid & 15;
    float acc = bias[co];
#pragma unroll 8
    for (int ci = 0; ci < 256; ci++)
        acc += xsh[ci * 16 + p] * wsh[co * 256 + ci];
    out[(size_t)b * 256 + co * 16 + p] = fmaxf(acc, 0.f);
}

// =====================================================================
// MLP head
// =====================================================================
__global__ __launch_bounds__(128) void mlp_kernel(
    const float* __restrict__ hsum, const float* __restrict__ feat,
    const float* __restrict__ w1, const float* __restrict__ b1,
    const float* __restrict__ w2, const float* __restrict__ b2,
    const float* __restrict__ w3, const float* __restrict__ b3,
    float* __restrict__ out)
{
    __shared__ float zin[512];
    __shared__ float z1[128];
    __shared__ float z2[32];
    int b = blockIdx.x, tid = threadIdx.x;
    for (int i = tid; i < 256; i += 128) {
        zin[i]       = hsum[(size_t)b * 256 + i] * (1.f / 128.f);
        zin[256 + i] = feat[(size_t)b * 256 + i];
    }
    __syncthreads();
    {
        const float* wr = w1 + (size_t)tid * 512;
        float acc = 0.f;
#pragma unroll 4
        for (int k = 0; k < 512; k += 4) {
            float4 wv = *(const float4*)(wr + k);
            float4 xv = *(const float4*)(&zin[k]);
            acc += wv.x * xv.x + wv.y * xv.y + wv.z * xv.z + wv.w * xv.w;
        }
        z1[tid] = fmaxf(acc + b1[tid], 0.f);
    }
    __syncthreads();
    if (tid < 32) {
        const float* wr = w2 + (size_t)tid * 128;
        float acc = 0.f;
#pragma unroll
        for (int k = 0; k < 128; k += 4) {
            float4 wv = *(const float4*)(wr + k);
            float4 xv = *(const float4*)(&z1[k]);
            acc += wv.x * xv.x + wv.y * xv.y + wv.z * xv.z + wv.w * xv.w;
        }
        z2[tid] = fmaxf(acc + b2[tid], 0.f);
    }
    __syncthreads();
    if (tid < 2) {
        const float* wr = w3 + (size_t)tid * 32;
        float acc = 0.f;
#pragma unroll
        for (int k = 0; k < 32; k++) acc += wr[k] * z2[k];
        out[(size_t)b * 2 + tid] = fmaxf(acc + b3[tid], 0.f);
    }
}

// =====================================================================
// host launcher
// =====================================================================
extern "C" void kernel_launch(void* const* d_in, const int* in_sizes, int n_in,
                              void* d_out, int out_size)
{
    const float* x    = (const float*)d_in[0];
    const float* w_ih = (const float*)d_in[1];
    const float* w_hh = (const float*)d_in[2];
    const float* b_ih = (const float*)d_in[3];
    const float* b_hh = (const float*)d_in[4];
    const float* c1w  = (const float*)d_in[5];
    const float* c1b  = (const float*)d_in[6];
    const float* c2w  = (const float*)d_in[7];
    const float* c2b  = (const float*)d_in[8];
    const float* c3w  = (const float*)d_in[9];
    const float* c3b  = (const float*)d_in[10];
    const float* c4w  = (const float*)d_in[11];
    const float* c4b  = (const float*)d_in[12];
    const float* f1w  = (const float*)d_in[13];
    const float* f1b  = (const float*)d_in[14];
    const float* f2w  = (const float*)d_in[15];
    const float* f2b  = (const float*)d_in[16];
    const float* f3w  = (const float*)d_in[17];
    const float* f3b  = (const float*)d_in[18];
    float* out = (float*)d_out;

    float *gatesx, *hA, *hB, *c, *hsum, *y1, *y2, *y3, *feat;
    cudaGetSymbolAddress((void**)&gatesx, g_gatesx);
    cudaGetSymbolAddress((void**)&hA,     g_hA);
    cudaGetSymbolAddress((void**)&hB,     g_hB);
    cudaGetSymbolAddress((void**)&c,      g_c);
    cudaGetSymbolAddress((void**)&hsum,   g_hsum);
    cudaGetSymbolAddress((void**)&y1,     g_y1);
    cudaGetSymbolAddress((void**)&y2,     g_y2);
    cudaGetSymbolAddress((void**)&y3,     g_y3);
    cudaGetSymbolAddress((void**)&feat,   g_feat);

    const int SM1 = (16 * 137 + 112 * W1PITCH) * 4;   // ~67.9 KB
    const int SM2 = (32 * 69 + 64 * 160) * 4;
    const int SM3 = (64 * 37 + 128 * 192) * 4;
    cudaFuncSetAttribute(conv1_kernel, cudaFuncAttributeMaxDynamicSharedMemorySize, SM1);
    cudaFuncSetAttribute(conv2_kernel, cudaFuncAttributeMaxDynamicSharedMemorySize, SM2);
    cudaFuncSetAttribute(conv3_kernel, cudaFuncAttributeMaxDynamicSharedMemorySize, SM3);

    // ---- CNN branch ----
    conv1_kernel<<<dim3(BB, 2), 256, SM1>>>(x, c1w, c1b, y1);
    conv2_kernel<<<BB, 256, SM2>>>(y1, c2w, c2b, y2);
    conv3_kernel<<<dim3(BB, 2), 256, SM3>>>(y2, c3w, c3b, y3);
    conv4_kernel<<<BB, 256>>>(y3, c4w, c4b, feat);

    // ---- input projection: gates_x = x @ w_ih^T + b_ih + b_hh ----
    xproj_kernel<<<dim3(G4 / 128, (BB * LL) / 128), 256>>>(
        x, w_ih, b_ih, b_hh, gatesx);

    // ---- LSTM recurrence: fused GEMM + cell per step ----
    lstm_init_kernel<<<BB, 256>>>(hA, c, hsum);
    for (int t = 0; t < LL; t++) {
        const float* hp = (t & 1) ? hB : hA;
        float*       hn = (t & 1) ? hA : hB;
        lstm_step_kernel<<<dim3(LHID / 16, BB / 64), 256>>>(
            hp, hn, c, hsum, w_hh, gatesx, t);
    }

    // ---- MLP head ----
    mlp_kernel<<<BB, 128>>>(hsum, feat, f1w, f1b, f2w, f2b, f3w, f3b, out);
}

// round 9
// speedup vs baseline: 2.4125x; 1.4191x over previous
#include <cuda_runtime.h>
#include <cuda_bf16.h>
#include <math.h>

// ---------------- problem dims ----------------
#define BB   512
#define LL   128
#define HH   768
#define LHID 256
#define G4   1024   // 4*LHID

typedef unsigned long long ull;
typedef unsigned int u32;

// ---------------- device scratch (no allocs allowed) ----------------
__device__ float g_gatesx[(size_t)BB * LL * G4];          // 256 MB
__device__ __nv_bfloat16 g_xE  [(size_t)BB * LL * 1536];  // [ah|al]
__device__ __nv_bfloat16 g_wihE[(size_t)G4 * 1536];       // [bh|bl]
__device__ __nv_bfloat16 g_wc1E[(size_t)7 * 256 * 1536];  // per-kw [bh|bl]
__device__ float g_hA  [(size_t)BB * LHID];
__device__ float g_hB  [(size_t)BB * LHID];
__device__ float g_c   [(size_t)BB * LHID];
__device__ float g_hsum[(size_t)BB * LHID];
__device__ float g_y1  [(size_t)BB * 256 * 64];
__device__ float g_y2  [(size_t)BB * 64 * 32];
__device__ float g_y3  [(size_t)BB * 256 * 16];
__device__ float g_feat[(size_t)BB * 256];

// ---------------- helpers ----------------
__device__ __forceinline__ float sigf(float x) { return 1.f / (1.f + expf(-x)); }
__device__ __forceinline__ ull pack2(float lo, float hi) {
    ull r; asm("mov.b64 %0, {%1, %2};" : "=l"(r) : "f"(lo), "f"(hi)); return r;
}
__device__ __forceinline__ ull bcast2(float v) { return pack2(v, v); }
__device__ __forceinline__ void fma2(ull& d, ull a, ull b) {
    asm("fma.rn.f32x2 %0, %1, %2, %0;" : "+l"(d) : "l"(a), "l"(b));
}
__device__ __forceinline__ float2 unpack2(ull v) {
    float2 r; asm("mov.b64 {%0, %1}, %2;" : "=f"(r.x), "=f"(r.y) : "l"(v)); return r;
}
__device__ __forceinline__ u32 smem_u32(const void* p) {
    u32 a; asm("{ .reg .u64 t; cvta.to.shared.u64 t, %1; cvt.u32.u64 %0, t; }"
               : "=r"(a) : "l"(p));
    return a;
}
__device__ __forceinline__ void cpa16(u32 dst, const void* src, bool valid) {
    asm volatile("cp.async.cg.shared.global [%0], [%1], 16, %2;"
                 :: "r"(dst), "l"(src), "r"(valid ? 16 : 0));
}
#define CPA_COMMIT() asm volatile("cp.async.commit_group;" ::: "memory")
#define CPA_WAIT0()  asm volatile("cp.async.wait_group 0;" ::: "memory")

__device__ __forceinline__ void ldmx4(u32& a0, u32& a1, u32& a2, u32& a3, u32 addr) {
    asm volatile("ldmatrix.sync.aligned.m8n8.x4.shared.b16 {%0,%1,%2,%3}, [%4];"
                 : "=r"(a0), "=r"(a1), "=r"(a2), "=r"(a3) : "r"(addr));
}
__device__ __forceinline__ void mma16816(float* d, const u32* a, const u32* b) {
    asm volatile(
        "mma.sync.aligned.m16n8k16.row.col.f32.bf16.bf16.f32 "
        "{%0,%1,%2,%3}, {%4,%5,%6,%7}, {%8,%9}, {%0,%1,%2,%3};"
        : "+f"(d[0]), "+f"(d[1]), "+f"(d[2]), "+f"(d[3])
        : "r"(a[0]), "r"(a[1]), "r"(a[2]), "r"(a[3]), "r"(b[0]), "r"(b[1]));
}

// =====================================================================
// expand: fp32 [rows,768] -> bf16 [rows,1536] as [hi block | lo block]
// =====================================================================
__global__ __launch_bounds__(256) void expand_hl(
    const float* __restrict__ src, __nv_bfloat16* __restrict__ dst, int total4)
{
    int i = blockIdx.x * 256 + threadIdx.x;
    if (i >= total4) return;
    int r = i / 192, g = i - r * 192;
    float4 v = *(const float4*)(src + (size_t)r * 768 + g * 4);
    __nv_bfloat162 h01, h23, l01, l23;
    h01.x = __float2bfloat16(v.x); h01.y = __float2bfloat16(v.y);
    h23.x = __float2bfloat16(v.z); h23.y = __float2bfloat16(v.w);
    l01.x = __float2bfloat16(v.x - __bfloat162float(h01.x));
    l01.y = __float2bfloat16(v.y - __bfloat162float(h01.y));
    l23.x = __float2bfloat16(v.z - __bfloat162float(h23.x));
    l23.y = __float2bfloat16(v.w - __bfloat162float(h23.y));
    uint2 uh, ul;
    uh.x = *(u32*)&h01; uh.y = *(u32*)&h23;
    ul.x = *(u32*)&l01; ul.y = *(u32*)&l23;
    *(uint2*)(dst + (size_t)r * 1536 + g * 4)       = uh;
    *(uint2*)(dst + (size_t)r * 1536 + 768 + g * 4) = ul;
}

// conv1 weights [256, 768, 7] -> per-kw [256, 1536] as [hi|lo]
__global__ __launch_bounds__(256) void expand_c1w(
    const float* __restrict__ w, __nv_bfloat16* __restrict__ dst)
{
    int idx = blockIdx.x * 256 + threadIdx.x;
    if (idx >= 256 * 768) return;
    int co = idx / 768, ci = idx - co * 768;
#pragma unroll
    for (int kw = 0; kw < 7; kw++) {
        float v = w[(size_t)(co * 768 + ci) * 7 + kw];
        __nv_bfloat16 h = __float2bfloat16(v);
        __nv_bfloat16 l = __float2bfloat16(v - __bfloat162float(h));
        size_t base = ((size_t)kw * 256 + co) * 1536;
        dst[base + ci]       = h;
        dst[base + 768 + ci] = l;
    }
}

// =====================================================================
// HMMA GEMM (mma.sync bf16): C tile 128x128, BK=64-bf16 chunks.
// 256 thr = 8 warps (4m x 2n), warp tile 32m x 64n, m16n8k16 frags.
// mode 0: xproj  out[m][n] = A@B^T + b0 + b1
// mode 1: conv1  accumulate 7 shifted GEMMs; epilogue bias+pool2(m)+relu
// smem: double-buffered A/B, pitch 72 halves (144B) per row.
// =====================================================================
#define KP 72
#define TILEH (128 * KP)              // halves per matrix buffer
#define SMEMB (4 * TILEH * 2)         // 73728 bytes

__global__ __launch_bounds__(256) void gemm_mma(
    const __nv_bfloat16* __restrict__ A,
    const __nv_bfloat16* __restrict__ Bw,
    const float* __restrict__ bias0, const float* __restrict__ bias1,
    const float* __restrict__ biasC,
    float* __restrict__ out, int mode, int nchunks)
{
    extern __shared__ __align__(16) __nv_bfloat16 sm[];
    const int tid  = threadIdx.x;
    const int lane = tid & 31;
    const int warp = tid >> 5;
    const int wm = (warp & 3) * 32;
    const int wn = (warp >> 2) * 64;
    const int m0 = blockIdx.y * 128;
    const int n0 = blockIdx.x * 128;

    float acc[2][8][4];
#pragma unroll
    for (int mf = 0; mf < 2; mf++)
#pragma unroll
        for (int j = 0; j < 8; j++)
#pragma unroll
            for (int e = 0; e < 4; e++) acc[mf][j][e] = 0.f;

    // ---- async stage of chunk cc into buffer buf ----
    auto stage = [&](int cc, int buf) {
        int kw = 0, c = cc;
        if (mode) { kw = cc / 36; c = cc - kw * 36; }
        int acol = (c < 12) ? c * 64 : (c < 24) ? 768 + (c - 12) * 64 : (c - 24) * 64;
        int bcol = (c < 12) ? c * 64 : (c < 24) ? (c - 12) * 64 : 768 + (c - 24) * 64;
        const __nv_bfloat16* Bp = Bw + (mode ? (size_t)kw * 256 * 1536 : (size_t)0);
        u32 abase = smem_u32(sm + (size_t)buf * 2 * TILEH);
        u32 bbase = abase + TILEH * 2;
#pragma unroll
        for (int r = 0; r < 4; r++) {
            int idx = tid + r * 256;
            int row = idx >> 3, g = idx & 7;
            bool ok = true;
            const __nv_bfloat16* src;
            if (mode) {
                int p = row + kw - 3;
                ok = (p >= 0 && p < 128);
                src = A + (size_t)(m0 + (ok ? p : 0)) * 1536 + acol + g * 8;
            } else {
                src = A + (size_t)(m0 + row) * 1536 + acol + g * 8;
            }
            cpa16(abase + (row * KP + g * 8) * 2, src, ok);
        }
#pragma unroll
        for (int r = 0; r < 4; r++) {
            int idx = tid + r * 256;
            int row = idx >> 3, g = idx & 7;
            cpa16(bbase + (row * KP + g * 8) * 2,
                  Bp + (size_t)(n0 + row) * 1536 + bcol + g * 8, true);
        }
        CPA_COMMIT();
    };

    stage(0, 0);

    for (int cc = 0; cc < nchunks; cc++) {
        const int buf = cc & 1;
        CPA_WAIT0();
        __syncthreads();
        if (cc + 1 < nchunks) stage(cc + 1, 1 - buf);

        const __nv_bfloat16* Asb = sm + (size_t)buf * 2 * TILEH;
        const __nv_bfloat16* Bsb = Asb + TILEH;
        u32 abase = smem_u32(Asb);
#pragma unroll
        for (int k16 = 0; k16 < 4; k16++) {
            const int kh = k16 * 16;
            u32 a[2][4];
#pragma unroll
            for (int mf = 0; mf < 2; mf++) {
                u32 ad = abase +
                    ((wm + 16 * mf + (lane & 15)) * KP + kh + 8 * (lane >> 4)) * 2;
                ldmx4(a[mf][0], a[mf][1], a[mf][2], a[mf][3], ad);
            }
            u32 b[8][2];
#pragma unroll
            for (int j = 0; j < 8; j++) {
                const u32* p = (const u32*)(Bsb + (wn + 8 * j + (lane >> 2)) * KP + kh)
                               + (lane & 3);
                b[j][0] = p[0];
                b[j][1] = p[4];
            }
#pragma unroll
            for (int mf = 0; mf < 2; mf++)
#pragma unroll
                for (int j = 0; j < 8; j++)
                    mma16816(acc[mf][j], a[mf], b[j]);
        }
        __syncthreads();
    }

    // ---- epilogue ----
    if (mode == 0) {
#pragma unroll
        for (int mf = 0; mf < 2; mf++) {
            int r = wm + 16 * mf + (lane >> 2);
#pragma unroll
            for (int j = 0; j < 8; j++) {
                int n = n0 + wn + 8 * j + 2 * (lane & 3);
                float bs0 = bias0[n] + bias1[n];
                float bs1 = bias0[n + 1] + bias1[n + 1];
                float2 v0 = make_float2(acc[mf][j][0] + bs0, acc[mf][j][1] + bs1);
                float2 v1 = make_float2(acc[mf][j][2] + bs0, acc[mf][j][3] + bs1);
                *(float2*)&out[(size_t)(m0 + r) * G4 + n]     = v0;
                *(float2*)&out[(size_t)(m0 + r + 8) * G4 + n] = v1;
            }
        }
    } else {
        const int b = blockIdx.y;
        float* ob = out + (size_t)b * 256 * 64;
#pragma unroll
        for (int mf = 0; mf < 2; mf++) {
            int r = wm + 16 * mf + (lane >> 2);
#pragma unroll
            for (int j = 0; j < 8; j++) {
                int co = n0 + wn + 8 * j + 2 * (lane & 3);
                float d0 = acc[mf][j][0] + biasC[co];
                float d1 = acc[mf][j][1] + biasC[co + 1];
                float d2 = acc[mf][j][2] + biasC[co];
                float d3 = acc[mf][j][3] + biasC[co + 1];
                float o0 = __shfl_xor_sync(0xffffffffu, d0, 4);
                float o1 = __shfl_xor_sync(0xffffffffu, d1, 4);
                float o2 = __shfl_xor_sync(0xffffffffu, d2, 4);
                float o3 = __shfl_xor_sync(0xffffffffu, d3, 4);
                if (!(lane & 4)) {
                    int q0 = r >> 1, q1 = (r + 8) >> 1;
                    ob[(size_t)co * 64 + q0]       = fmaxf(fmaxf(d0, o0), 0.f);
                    ob[(size_t)(co + 1) * 64 + q0] = fmaxf(fmaxf(d1, o1), 0.f);
                    ob[(size_t)co * 64 + q1]       = fmaxf(fmaxf(d2, o2), 0.f);
                    ob[(size_t)(co + 1) * 64 + q1] = fmaxf(fmaxf(d3, o3), 0.f);
                }
            }
        }
    }
}

// =====================================================================
// Fused LSTM step (unchanged — passes)
// =====================================================================
__global__ __launch_bounds__(256) void lstm_step_kernel(
    const float* __restrict__ hprev, float* __restrict__ hnext,
    float* __restrict__ c, float* __restrict__ hsum,
    const float* __restrict__ whh, const float* __restrict__ gx, int t)
{
    __shared__ __align__(16) float As[32 * 68];
    __shared__ __align__(16) float Bs[32 * 68];
    const int tid = threadIdx.x;
    const int j0 = blockIdx.x * 16;
    const int b0 = blockIdx.y * 64;
    const int tx = tid & 15;
    const int ty = tid >> 4;

    ull acc[2][4];
#pragma unroll
    for (int i = 0; i < 2; i++)
#pragma unroll
        for (int g = 0; g < 4; g++) acc[i][g] = 0ULL;

    for (int k0 = 0; k0 < LHID; k0 += 32) {
        for (int idx = tid; idx < 64 * 32; idx += 256) {
            int bb = idx >> 5, k = idx & 31;
            As[k * 68 + bb] = hprev[(size_t)(b0 + bb) * LHID + k0 + k];
        }
        for (int idx = tid; idx < 64 * 32; idx += 256) {
            int n = idx >> 5, k = idx & 31;
            int grow = (n >> 4) * LHID + j0 + (n & 15);
            Bs[k * 68 + n] = whh[(size_t)grow * LHID + k0 + k];
        }
        __syncthreads();
#pragma unroll
        for (int kk = 0; kk < 32; kk++) {
            ulonglong2 ap = *(const ulonglong2*)&As[kk * 68 + ty * 4];
            ull p0 = bcast2(Bs[kk * 68 + tx]);
            ull p1 = bcast2(Bs[kk * 68 + 16 + tx]);
            ull p2 = bcast2(Bs[kk * 68 + 32 + tx]);
            ull p3 = bcast2(Bs[kk * 68 + 48 + tx]);
            fma2(acc[0][0], ap.x, p0); fma2(acc[1][0], ap.y, p0);
            fma2(acc[0][1], ap.x, p1); fma2(acc[1][1], ap.y, p1);
            fma2(acc[0][2], ap.x, p2); fma2(acc[1][2], ap.y, p2);
            fma2(acc[0][3], ap.x, p3); fma2(acc[1][3], ap.y, p3);
        }
        __syncthreads();
    }

    const int j = j0 + tx;
#pragma unroll
    for (int bp = 0; bp < 2; bp++) {
        float2 vi = unpack2(acc[bp][0]);
        float2 vf = unpack2(acc[bp][1]);
        float2 vg = unpack2(acc[bp][2]);
        float2 vo = unpack2(acc[bp][3]);
#pragma unroll
        for (int hf = 0; hf < 2; hf++) {
            int b = b0 + ty * 4 + bp * 2 + hf;
            float gi = hf ? vi.y : vi.x;
            float gf = hf ? vf.y : vf.x;
            float gg = hf ? vg.y : vg.x;
            float go = hf ? vo.y : vo.x;
            size_t gxo = ((size_t)b * LL + t) * G4 + j;
            float i_ = sigf(gi + gx[gxo]);
            float f_ = sigf(gf + gx[gxo + 256]);
            float g_ = tanhf(gg + gx[gxo + 512]);
            float o_ = sigf(go + gx[gxo + 768]);
            int ci = b * LHID + j;
            float cn = f_ * c[ci] + i_ * g_;
            c[ci] = cn;
            float hn = o_ * tanhf(cn);
            hnext[ci] = hn;
            hsum[ci] += hn;
        }
    }
}

__global__ void lstm_init_kernel(float* h, float* c, float* s)
{
    int idx = blockIdx.x * 256 + threadIdx.x;
    h[idx] = 0.f; c[idx] = 0.f; s[idx] = 0.f;
}

// =====================================================================
// conv2/3/4 + mlp (unchanged — pass)
// =====================================================================
__global__ __launch_bounds__(256) void conv2_kernel(
    const float* __restrict__ in, const float* __restrict__ w,
    const float* __restrict__ bias, float* __restrict__ out)
{
    extern __shared__ float smf[];
    float* xs = smf;
    float* ws = smf + 32 * 69;
    const int b = blockIdx.x;
    const int tid = threadIdx.x;
    const int lane = tid & 31;
    const int cog  = tid >> 5;

    float acc[8][2];
#pragma unroll
    for (int j = 0; j < 8; j++) { acc[j][0] = 0.f; acc[j][1] = 0.f; }

    const float* ib = in + (size_t)b * 256 * 64;

    for (int ci0 = 0; ci0 < 256; ci0 += 32) {
        for (int idx = tid; idx < 32 * 68; idx += 256) {
            int cil = idx / 68, s = idx - cil * 68;
            int p = s - 2;
            xs[cil * 69 + s] =
                (p >= 0 && p < 64) ? ib[(size_t)(ci0 + cil) * 64 + p] : 0.f;
        }
        for (int idx = tid; idx < 64 * 160; idx += 256) {
            int col = idx / 160, r = idx - col * 160;
            ws[idx] = w[(size_t)col * (256 * 5) + ci0 * 5 + r];
        }
        __syncthreads();

        for (int ci = 0; ci < 32; ci++) {
            const float* xr = &xs[ci * 69 + lane];
            const float* wr = &ws[cog * 160 + ci * 5];
#pragma unroll
            for (int kw = 0; kw < 5; kw++) {
                float xv0 = xr[kw];
                float xv1 = xr[kw + 32];
#pragma unroll
                for (int j = 0; j < 8; j++) {
                    float wv = wr[j * (8 * 160) + kw];
                    acc[j][0] += wv * xv0;
                    acc[j][1] += wv * xv1;
                }
            }
        }
        __syncthreads();
    }

#pragma unroll
    for (int j = 0; j < 8; j++) {
        int co = cog + 8 * j;
        float bv = bias[co];
#pragma unroll
        for (int i = 0; i < 2; i++) {
            float v = acc[j][i] + bv;
            float o = __shfl_xor_sync(0xffffffffu, v, 1);
            float m = fmaxf(v, o);
            if (!(lane & 1)) {
                int q = (lane >> 1) + 16 * i;
                out[(size_t)b * 64 * 32 + (size_t)co * 32 + q] = fmaxf(m, 0.f);
            }
        }
    }
}

__global__ __launch_bounds__(256) void conv3_kernel(
    const float* __restrict__ in, const float* __restrict__ w,
    const float* __restrict__ bias, float* __restrict__ out)
{
    extern __shared__ float smf[];
    float* xs = smf;
    float* ws = smf + 64 * 37;
    const int b   = blockIdx.x;
    const int co0 = blockIdx.y * 128;
    const int tid = threadIdx.x;
    const int lane = tid & 31;
    const int cog  = tid >> 5;

    float acc[16];
#pragma unroll
    for (int j = 0; j < 16; j++) acc[j] = 0.f;

    const float* ib = in + (size_t)b * 64 * 32;

    for (int idx = tid; idx < 64 * 34; idx += 256) {
        int cil = idx / 34, s = idx - cil * 34;
        int p = s - 1;
        xs[cil * 37 + s] = (p >= 0 && p < 32) ? ib[(size_t)cil * 32 + p] : 0.f;
    }
    for (int idx = tid; idx < 128 * 192; idx += 256) {
        int col = idx / 192, r = idx - col * 192;
        ws[idx] = w[(size_t)(co0 + col) * 192 + r];
    }
    __syncthreads();

    for (int ci = 0; ci < 64; ci++) {
        const float* xr = &xs[ci * 37 + lane];
        float xv0 = xr[0], xv1 = xr[1], xv2 = xr[2];
        const float* wr = &ws[cog * 192 + ci * 3];
#pragma unroll
        for (int j = 0; j < 16; j++) {
            const float* wj = wr + j * (8 * 192);
            acc[j] += wj[0] * xv0 + wj[1] * xv1 + wj[2] * xv2;
        }
    }

#pragma unroll
    for (int j = 0; j < 16; j++) {
        int co = co0 + cog + 8 * j;
        float v = acc[j] + bias[co];
        float o = __shfl_xor_sync(0xffffffffu, v, 1);
        float m = fmaxf(v, o);
        if (!(lane & 1)) {
            int q = lane >> 1;
            out[(size_t)b * 256 * 16 + (size_t)co * 16 + q] = fmaxf(m, 0.f);
        }
    }
}

__global__ __launch_bounds__(256) void conv4_kernel(
    const float* __restrict__ in, const float* __restrict__ w,
    const float* __restrict__ bias, float* __restrict__ out)
{
    __shared__ float xsh[4096];
    __shared__ float wsh[4096];
    int b = blockIdx.x, tid = threadIdx.x;
    const float* ib = in + (size_t)b * 4096;
    for (int i = tid; i < 4096; i += 256) { xsh[i] = ib[i]; wsh[i] = w[i]; }
    __syncthreads();
    int co = tid >> 4, p = tid & 15;
    float acc = bias[co];
#pragma unroll 8
    for (int ci = 0; ci < 256; ci++)
        acc += xsh[ci * 16 + p] * wsh[co * 256 + ci];
    out[(size_t)b * 256 + co * 16 + p] = fmaxf(acc, 0.f);
}

__global__ __launch_bounds__(128) void mlp_kernel(
    const float* __restrict__ hsum, const float* __restrict__ feat,
    const float* __restrict__ w1, const float* __restrict__ b1,
    const float* __restrict__ w2, const float* __restrict__ b2,
    const float* __restrict__ w3, const float* __restrict__ b3,
    float* __restrict__ out)
{
    __shared__ float zin[512];
    __shared__ float z1[128];
    __shared__ float z2[32];
    int b = blockIdx.x, tid = threadIdx.x;
    for (int i = tid; i < 256; i += 128) {
        zin[i]       = hsum[(size_t)b * 256 + i] * (1.f / 128.f);
        zin[256 + i] = feat[(size_t)b * 256 + i];
    }
    __syncthreads();
    {
        const float* wr = w1 + (size_t)tid * 512;
        float acc = 0.f;
#pragma unroll 4
        for (int k = 0; k < 512; k += 4) {
            float4 wv = *(const float4*)(wr + k);
            float4 xv = *(const float4*)(&zin[k]);
            acc += wv.x * xv.x + wv.y * xv.y + wv.z * xv.z + wv.w * xv.w;
        }
        z1[tid] = fmaxf(acc + b1[tid], 0.f);
    }
    __syncthreads();
    if (tid < 32) {
        const float* wr = w2 + (size_t)tid * 128;
        float acc = 0.f;
#pragma unroll
        for (int k = 0; k < 128; k += 4) {
            float4 wv = *(const float4*)(wr + k);
            float4 xv = *(const float4*)(&z1[k]);
            acc += wv.x * xv.x + wv.y * xv.y + wv.z * xv.z + wv.w * xv.w;
        }
        z2[tid] = fmaxf(acc + b2[tid], 0.f);
    }
    __syncthreads();
    if (tid < 2) {
        const float* wr = w3 + (size_t)tid * 32;
        float acc = 0.f;
#pragma unroll
        for (int k = 0; k < 32; k++) acc += wr[k] * z2[k];
        out[(size_t)b * 2 + tid] = fmaxf(acc + b3[tid], 0.f);
    }
}

// =====================================================================
// host launcher
// =====================================================================
extern "C" void kernel_launch(void* const* d_in, const int* in_sizes, int n_in,
                              void* d_out, int out_size)
{
    const float* x    = (const float*)d_in[0];
    const float* w_ih = (const float*)d_in[1];
    const float* w_hh = (const float*)d_in[2];
    const float* b_ih = (const float*)d_in[3];
    const float* b_hh = (const float*)d_in[4];
    const float* c1w  = (const float*)d_in[5];
    const float* c1b  = (const float*)d_in[6];
    const float* c2w  = (const float*)d_in[7];
    const float* c2b  = (const float*)d_in[8];
    const float* c3w  = (const float*)d_in[9];
    const float* c3b  = (const float*)d_in[10];
    const float* c4w  = (const float*)d_in[11];
    const float* c4b  = (const float*)d_in[12];
    const float* f1w  = (const float*)d_in[13];
    const float* f1b  = (const float*)d_in[14];
    const float* f2w  = (const float*)d_in[15];
    const float* f2b  = (const float*)d_in[16];
    const float* f3w  = (const float*)d_in[17];
    const float* f3b  = (const float*)d_in[18];
    float* out = (float*)d_out;

    float *gatesx, *hA, *hB, *c, *hsum, *y1, *y2, *y3, *feat;
    __nv_bfloat16 *xE, *wihE, *wc1E;
    cudaGetSymbolAddress((void**)&gatesx, g_gatesx);
    cudaGetSymbolAddress((void**)&xE,     g_xE);
    cudaGetSymbolAddress((void**)&wihE,   g_wihE);
    cudaGetSymbolAddress((void**)&wc1E,   g_wc1E);
    cudaGetSymbolAddress((void**)&hA,     g_hA);
    cudaGetSymbolAddress((void**)&hB,     g_hB);
    cudaGetSymbolAddress((void**)&c,      g_c);
    cudaGetSymbolAddress((void**)&hsum,   g_hsum);
    cudaGetSymbolAddress((void**)&y1,     g_y1);
    cudaGetSymbolAddress((void**)&y2,     g_y2);
    cudaGetSymbolAddress((void**)&y3,     g_y3);
    cudaGetSymbolAddress((void**)&feat,   g_feat);

    const int SM2 = (32 * 69 + 64 * 160) * 4;
    const int SM3 = (64 * 37 + 128 * 192) * 4;
    cudaFuncSetAttribute(conv2_kernel, cudaFuncAttributeMaxDynamicSharedMemorySize, SM2);
    cudaFuncSetAttribute(conv3_kernel, cudaFuncAttributeMaxDynamicSharedMemorySize, SM3);
    cudaFuncSetAttribute(gemm_mma, cudaFuncAttributeMaxDynamicSharedMemorySize, SMEMB);

    // ---- bf16 hi/lo expansion (x shared by conv1 & xproj) ----
    expand_hl<<<(BB * LL * 192 + 255) / 256, 256>>>(x, xE, BB * LL * 192);
    expand_hl<<<(G4 * 192 + 255) / 256, 256>>>(w_ih, wihE, G4 * 192);
    expand_c1w<<<(256 * 768 + 255) / 256, 256>>>(c1w, wc1E);

    // ---- conv1 via 7 accumulated HMMA GEMMs (252 chunks) ----
    gemm_mma<<<dim3(2, BB), 256, SMEMB>>>(
        xE, wc1E, nullptr, nullptr, c1b, y1, 1, 7 * 36);

    // ---- rest of CNN ----
    conv2_kernel<<<BB, 256, SM2>>>(y1, c2w, c2b, y2);
    conv3_kernel<<<dim3(BB, 2), 256, SM3>>>(y2, c3w, c3b, y3);
    conv4_kernel<<<BB, 256>>>(y3, c4w, c4b, feat);

    // ---- input projection via HMMA (36 chunks) ----
    gemm_mma<<<dim3(G4 / 128, (BB * LL) / 128), 256, SMEMB>>>(
        xE, wihE, b_ih, b_hh, nullptr, gatesx, 0, 36);

    // ---- LSTM recurrence ----
    lstm_init_kernel<<<BB, 256>>>(hA, c, hsum);
    for (int t = 0; t < LL; t++) {
        const float* hp = (t & 1) ? hB : hA;
        float*       hn = (t & 1) ? hA : hB;
        lstm_step_kernel<<<dim3(LHID / 16, BB / 64), 256>>>(
            hp, hn, c, hsum, w_hh, gatesx, t);
    }

    // ---- MLP head ----
    mlp_kernel<<<BB, 128>>>(hsum, feat, f1w, f1b, f2w, f2b, f3w, f3b, out);
}

// round 12
// speedup vs baseline: 2.8538x; 1.1829x over previous
#include <cuda_runtime.h>
#include <cuda_bf16.h>
#include <math.h>

// ---------------- problem dims ----------------
#define BB   512
#define LL   128
#define HH   768
#define LHID 256
#define G4   1024   // 4*LHID

typedef unsigned long long ull;
typedef unsigned int u32;

// ---------------- device scratch (no allocs allowed) ----------------
__device__ float g_gatesx[(size_t)BB * LL * G4];          // 256 MB
__device__ __nv_bfloat16 g_xE  [(size_t)BB * LL * 1536];  // [ah|al]
__device__ __nv_bfloat16 g_wihE[(size_t)G4 * 1536];       // [bh|bl]
__device__ __nv_bfloat16 g_wc1E[(size_t)7 * 256 * 1536];  // per-kw [bh|bl]
__device__ __nv_bfloat16 g_whhE[(size_t)G4 * 512];        // [bh|bl] over k=256
__device__ __nv_bfloat16 g_hEA [(size_t)BB * 512];        // h hi|lo ping
__device__ __nv_bfloat16 g_hEB [(size_t)BB * 512];        // h hi|lo pong
__device__ float g_c   [(size_t)BB * LHID];
__device__ float g_hsum[(size_t)BB * LHID];
__device__ float g_y1  [(size_t)BB * 256 * 64];
__device__ float g_y2  [(size_t)BB * 64 * 32];
__device__ float g_y3  [(size_t)BB * 256 * 16];
__device__ float g_feat[(size_t)BB * 256];

// ---------------- helpers ----------------
__device__ __forceinline__ float sigf(float x) { return 1.f / (1.f + expf(-x)); }
__device__ __forceinline__ u32 smem_u32(const void* p) {
    u32 a; asm("{ .reg .u64 t; cvta.to.shared.u64 t, %1; cvt.u32.u64 %0, t; }"
               : "=r"(a) : "l"(p));
    return a;
}
__device__ __forceinline__ void cpa16(u32 dst, const void* src, bool valid) {
    asm volatile("cp.async.cg.shared.global [%0], [%1], 16, %2;"
                 :: "r"(dst), "l"(src), "r"(valid ? 16 : 0));
}
#define CPA_COMMIT() asm volatile("cp.async.commit_group;" ::: "memory")
#define CPA_WAIT0()  asm volatile("cp.async.wait_group 0;" ::: "memory")

__device__ __forceinline__ void ldmx4(u32& a0, u32& a1, u32& a2, u32& a3, u32 addr) {
    asm volatile("ldmatrix.sync.aligned.m8n8.x4.shared.b16 {%0,%1,%2,%3}, [%4];"
                 : "=r"(a0), "=r"(a1), "=r"(a2), "=r"(a3) : "r"(addr));
}
__device__ __forceinline__ void mma16816(float* d, const u32* a, const u32* b) {
    asm volatile(
        "mma.sync.aligned.m16n8k16.row.col.f32.bf16.bf16.f32 "
        "{%0,%1,%2,%3}, {%4,%5,%6,%7}, {%8,%9}, {%0,%1,%2,%3};"
        : "+f"(d[0]), "+f"(d[1]), "+f"(d[2]), "+f"(d[3])
        : "r"(a[0]), "r"(a[1]), "r"(a[2]), "r"(a[3]), "r"(b[0]), "r"(b[1]));
}

// =====================================================================
// expand: fp32 [rows,768] -> bf16 [rows,1536] as [hi block | lo block]
// =====================================================================
__global__ __launch_bounds__(256) void expand_hl(
    const float* __restrict__ src, __nv_bfloat16* __restrict__ dst, int total4)
{
    int i = blockIdx.x * 256 + threadIdx.x;
    if (i >= total4) return;
    int r = i / 192, g = i - r * 192;
    float4 v = *(const float4*)(src + (size_t)r * 768 + g * 4);
    __nv_bfloat162 h01, h23, l01, l23;
    h01.x = __float2bfloat16(v.x); h01.y = __float2bfloat16(v.y);
    h23.x = __float2bfloat16(v.z); h23.y = __float2bfloat16(v.w);
    l01.x = __float2bfloat16(v.x - __bfloat162float(h01.x));
    l01.y = __float2bfloat16(v.y - __bfloat162float(h01.y));
    l23.x = __float2bfloat16(v.z - __bfloat162float(h23.x));
    l23.y = __float2bfloat16(v.w - __bfloat162float(h23.y));
    uint2 uh, ul;
    uh.x = *(u32*)&h01; uh.y = *(u32*)&h23;
    ul.x = *(u32*)&l01; ul.y = *(u32*)&l23;
    *(uint2*)(dst + (size_t)r * 1536 + g * 4)       = uh;
    *(uint2*)(dst + (size_t)r * 1536 + 768 + g * 4) = ul;
}

// conv1 weights [256, 768, 7] -> per-kw [256, 1536] as [hi|lo]
__global__ __launch_bounds__(256) void expand_c1w(
    const float* __restrict__ w, __nv_bfloat16* __restrict__ dst)
{
    int idx = blockIdx.x * 256 + threadIdx.x;
    if (idx >= 256 * 768) return;
    int co = idx / 768, ci = idx - co * 768;
#pragma unroll
    for (int kw = 0; kw < 7; kw++) {
        float v = w[(size_t)(co * 768 + ci) * 7 + kw];
        __nv_bfloat16 h = __float2bfloat16(v);
        __nv_bfloat16 l = __float2bfloat16(v - __bfloat162float(h));
        size_t base = ((size_t)kw * 256 + co) * 1536;
        dst[base + ci]       = h;
        dst[base + 768 + ci] = l;
    }
}

// w_hh [1024, 256] -> bf16 [1024, 512] = [hi | lo]
__global__ __launch_bounds__(256) void expand_whh(
    const float* __restrict__ w, __nv_bfloat16* __restrict__ dst)
{
    int idx = blockIdx.x * 256 + threadIdx.x;
    if (idx >= 1024 * 256) return;
    int n = idx >> 8, k = idx & 255;
    float v = w[idx];
    __nv_bfloat16 h = __float2bfloat16(v);
    dst[(size_t)n * 512 + k]       = h;
    dst[(size_t)n * 512 + 256 + k] = __float2bfloat16(v - __bfloat162float(h));
}

// zero h hi/lo ping buffer + c + hsum
__global__ __launch_bounds__(256) void lstm_init_kernel(
    __nv_bfloat16* hE, float* c, float* s)
{
    int idx = blockIdx.x * 256 + threadIdx.x;   // 512*256 = 131072
    c[idx] = 0.f; s[idx] = 0.f;
    ((u32*)hE)[idx] = 0u;                        // 262144 halves
}

// =====================================================================
// HMMA GEMM: C tile 128x128, BK=64-bf16 chunks, 8 warps (4m x 2n),
// warp tile 32m x 64n. B frags via ldmatrix.x4 (conflict-free @ pitch 72).
// mode 0: xproj  out = A@B^T + b0 + b1
// mode 1: conv1  7 shifted GEMMs accumulated (kw-inner chunk order);
//                epilogue bias + pool2(m) + relu
// =====================================================================
#define KP 72
#define TILEH (128 * KP)
#define SMEMB (4 * TILEH * 2)   // 73728 B

__global__ __launch_bounds__(256) void gemm_mma(
    const __nv_bfloat16* __restrict__ A,
    const __nv_bfloat16* __restrict__ Bw,
    const float* __restrict__ bias0, const float* __restrict__ bias1,
    const float* __restrict__ biasC,
    float* __restrict__ out, int mode, int nchunks)
{
    extern __shared__ __align__(16) __nv_bfloat16 sm[];
    const int tid  = threadIdx.x;
    const int lane = tid & 31;
    const int warp = tid >> 5;
    const int wm = (warp & 3) * 32;
    const int wn = (warp >> 2) * 64;
    const int m0 = blockIdx.y * 128;
    const int n0 = blockIdx.x * 128;

    float acc[2][8][4];
#pragma unroll
    for (int mf = 0; mf < 2; mf++)
#pragma unroll
        for (int j = 0; j < 8; j++)
#pragma unroll
            for (int e = 0; e < 4; e++) acc[mf][j][e] = 0.f;

    auto stage = [&](int cc, int buf) {
        int kw = 0, c = cc;
        if (mode) { kw = cc % 7; c = cc / 7; }   // kw-inner: A window L2-hot
        int acol = (c < 12) ? c * 64 : (c < 24) ? 768 + (c - 12) * 64 : (c - 24) * 64;
        int bcol = (c < 12) ? c * 64 : (c < 24) ? (c - 12) * 64 : 768 + (c - 24) * 64;
        const __nv_bfloat16* Bp = Bw + (mode ? (size_t)kw * 256 * 1536 : (size_t)0);
        u32 abase = smem_u32(sm + (size_t)buf * 2 * TILEH);
        u32 bbase = abase + TILEH * 2;
#pragma unroll
        for (int r = 0; r < 4; r++) {
            int idx = tid + r * 256;
            int row = idx >> 3, g = idx & 7;
            bool ok = true;
            const __nv_bfloat16* src;
            if (mode) {
                int p = row + kw - 3;
                ok = (p >= 0 && p < 128);
                src = A + (size_t)(m0 + (ok ? p : 0)) * 1536 + acol + g * 8;
            } else {
                src = A + (size_t)(m0 + row) * 1536 + acol + g * 8;
            }
            cpa16(abase + (row * KP + g * 8) * 2, src, ok);
        }
#pragma unroll
        for (int r = 0; r < 4; r++) {
            int idx = tid + r * 256;
            int row = idx >> 3, g = idx & 7;
            cpa16(bbase + (row * KP + g * 8) * 2,
                  Bp + (size_t)(n0 + row) * 1536 + bcol + g * 8, true);
        }
        CPA_COMMIT();
    };

    stage(0, 0);

    for (int cc = 0; cc < nchunks; cc++) {
        const int buf = cc & 1;
        CPA_WAIT0();
        __syncthreads();
        if (cc + 1 < nchunks) stage(cc + 1, 1 - buf);

        const __nv_bfloat16* Asb = sm + (size_t)buf * 2 * TILEH;
        const __nv_bfloat16* Bsb = Asb + TILEH;
        u32 abase = smem_u32(Asb);
        u32 bbase = smem_u32(Bsb);
#pragma unroll
        for (int k16 = 0; k16 < 4; k16++) {
            const int kh = k16 * 16;
            u32 a[2][4];
#pragma unroll
            for (int mf = 0; mf < 2; mf++) {
                u32 ad = abase +
                    ((wm + 16 * mf + (lane & 15)) * KP + kh + 8 * (lane >> 4)) * 2;
                ldmx4(a[mf][0], a[mf][1], a[mf][2], a[mf][3], ad);
            }
            u32 b[8][2];
            const int quad = lane >> 3, qr = lane & 7;
#pragma unroll
            for (int jj = 0; jj < 4; jj++) {
                u32 bd = bbase +
                    ((wn + 8 * (2 * jj + (quad >> 1)) + qr) * KP + kh + 8 * (quad & 1)) * 2;
                u32 r0, r1, r2, r3;
                ldmx4(r0, r1, r2, r3, bd);
                b[2 * jj][0] = r0; b[2 * jj][1] = r1;
                b[2 * jj + 1][0] = r2; b[2 * jj + 1][1] = r3;
            }
#pragma unroll
            for (int mf = 0; mf < 2; mf++)
#pragma unroll
                for (int j = 0; j < 8; j++)
                    mma16816(acc[mf][j], a[mf], b[j]);
        }
        __syncthreads();
    }

    // ---- epilogue ----
    if (mode == 0) {
#pragma unroll
        for (int mf = 0; mf < 2; mf++) {
            int r = wm + 16 * mf + (lane >> 2);
#pragma unroll
            for (int j = 0; j < 8; j++) {
                int n = n0 + wn + 8 * j + 2 * (lane & 3);
                float bs0 = bias0[n] + bias1[n];
                float bs1 = bias0[n + 1] + bias1[n + 1];
                float2 v0 = make_float2(acc[mf][j][0] + bs0, acc[mf][j][1] + bs1);
                float2 v1 = make_float2(acc[mf][j][2] + bs0, acc[mf][j][3] + bs1);
                *(float2*)&out[(size_t)(m0 + r) * G4 + n]     = v0;
                *(float2*)&out[(size_t)(m0 + r + 8) * G4 + n] = v1;
            }
        }
    } else {
        const int b = blockIdx.y;
        float* ob = out + (size_t)b * 256 * 64;
#pragma unroll
        for (int mf = 0; mf < 2; mf++) {
            int r = wm + 16 * mf + (lane >> 2);
#pragma unroll
            for (int j = 0; j < 8; j++) {
                int co = n0 + wn + 8 * j + 2 * (lane & 3);
                float d0 = acc[mf][j][0] + biasC[co];
                float d1 = acc[mf][j][1] + biasC[co + 1];
                float d2 = acc[mf][j][2] + biasC[co];
                float d3 = acc[mf][j][3] + biasC[co + 1];
                float o0 = __shfl_xor_sync(0xffffffffu, d0, 4);
                float o1 = __shfl_xor_sync(0xffffffffu, d1, 4);
                float o2 = __shfl_xor_sync(0xffffffffu, d2, 4);
                float o3 = __shfl_xor_sync(0xffffffffu, d3, 4);
                if (!(lane & 4)) {
                    int q0 = r >> 1, q1 = (r + 8) >> 1;
                    ob[(size_t)co * 64 + q0]       = fmaxf(fmaxf(d0, o0), 0.f);
                    ob[(size_t)(co + 1) * 64 + q0] = fmaxf(fmaxf(d1, o1), 0.f);
                    ob[(size_t)co * 64 + q1]       = fmaxf(fmaxf(d2, o2), 0.f);
                    ob[(size_t)(co + 1) * 64 + q1] = fmaxf(fmaxf(d3, o3), 0.f);
                }
            }
        }
    }
}

// =====================================================================
// HMMA LSTM step. gates[64b x 128n] tile; n = gate*32 + j (4 gates x 32 j).
// hprevE/whhE bf16 hi|lo, K = 3 terms x 4 chunks of 64 = 12 chunks.
// 8 warps (2m x 4n), warp tile 32m x 32n. Epilogue: smem f32 exchange ->
// fused cell update -> c, hsum, hnextE (hi/lo).
// Grid (8 jtiles, 8 btiles) = 64 blocks/step.
// =====================================================================
#define LAH (64 * KP)              // A halves
#define LBH (128 * KP)             // B halves
#define LBUF (LAH + LBH)           // per-buffer halves
#define SML (2 * LBUF * 2)         // 55296 B
#define PE 132

__global__ __launch_bounds__(256) void lstm_step_mma(
    const __nv_bfloat16* __restrict__ hprevE, __nv_bfloat16* __restrict__ hnextE,
    float* __restrict__ c, float* __restrict__ hsum,
    const __nv_bfloat16* __restrict__ whhE, const float* __restrict__ gx, int t)
{
    extern __shared__ __align__(16) __nv_bfloat16 sm[];
    const int tid  = threadIdx.x;
    const int lane = tid & 31;
    const int warp = tid >> 5;
    const int wm = (warp & 1) * 32;
    const int wn = (warp >> 1) * 32;
    const int j0 = blockIdx.x * 32;
    const int b0 = blockIdx.y * 64;

    float acc[2][4][4];
#pragma unroll
    for (int mf = 0; mf < 2; mf++)
#pragma unroll
        for (int j = 0; j < 4; j++)
#pragma unroll
            for (int e = 0; e < 4; e++) acc[mf][j][e] = 0.f;

    auto stage = [&](int cc, int buf) {
        int acol = (cc < 4) ? cc * 64 : (cc < 8) ? 256 + (cc - 4) * 64 : (cc - 8) * 64;
        int bcol = (cc < 4) ? cc * 64 : (cc < 8) ? (cc - 4) * 64 : 256 + (cc - 8) * 64;
        u32 abase = smem_u32(sm + (size_t)buf * LBUF);
        u32 bbase = abase + LAH * 2;
#pragma unroll
        for (int r = 0; r < 2; r++) {
            int idx = tid + r * 256;
            int row = idx >> 3, g = idx & 7;
            cpa16(abase + (row * KP + g * 8) * 2,
                  hprevE + (size_t)(b0 + row) * 512 + acol + g * 8, true);
        }
#pragma unroll
        for (int r = 0; r < 4; r++) {
            int idx = tid + r * 256;
            int row = idx >> 3, g = idx & 7;
            int wrow = (row >> 5) * 256 + j0 + (row & 31);
            cpa16(bbase + (row * KP + g * 8) * 2,
                  whhE + (size_t)wrow * 512 + bcol + g * 8, true);
        }
        CPA_COMMIT();
    };

    stage(0, 0);

    for (int cc = 0; cc < 12; cc++) {
        const int buf = cc & 1;
        CPA_WAIT0();
        __syncthreads();
        if (cc + 1 < 12) stage(cc + 1, 1 - buf);

        u32 abase = smem_u32(sm + (size_t)buf * LBUF);
        u32 bbase = abase + LAH * 2;
#pragma unroll
        for (int k16 = 0; k16 < 4; k16++) {
            const int kh = k16 * 16;
            u32 a[2][4];
#pragma unroll
            for (int mf = 0; mf < 2; mf++) {
                u32 ad = abase +
                    ((wm + 16 * mf + (lane & 15)) * KP + kh + 8 * (lane >> 4)) * 2;
                ldmx4(a[mf][0], a[mf][1], a[mf][2], a[mf][3], ad);
            }
            u32 b[4][2];
            const int quad = lane >> 3, qr = lane & 7;
#pragma unroll
            for (int jj = 0; jj < 2; jj++) {
                u32 bd = bbase +
                    ((wn + 8 * (2 * jj + (quad >> 1)) + qr) * KP + kh + 8 * (quad & 1)) * 2;
                u32 r0, r1, r2, r3;
                ldmx4(r0, r1, r2, r3, bd);
                b[2 * jj][0] = r0; b[2 * jj][1] = r1;
                b[2 * jj + 1][0] = r2; b[2 * jj + 1][1] = r3;
            }
#pragma unroll
            for (int mf = 0; mf < 2; mf++)
#pragma unroll
                for (int j = 0; j < 4; j++)
                    mma16816(acc[mf][j], a[mf], b[j]);
        }
        __syncthreads();
    }

    // ---- exchange gates through smem (overlay) ----
    float* sE = (float*)sm;
#pragma unroll
    for (int mf = 0; mf < 2; mf++) {
        int r = wm + 16 * mf + (lane >> 2);
#pragma unroll
        for (int j = 0; j < 4; j++) {
            int n = wn + 8 * j + 2 * (lane & 3);
            sE[r * PE + n]           = acc[mf][j][0];
            sE[r * PE + n + 1]       = acc[mf][j][1];
            sE[(r + 8) * PE + n]     = acc[mf][j][2];
            sE[(r + 8) * PE + n + 1] = acc[mf][j][3];
        }
    }
    __syncthreads();

    // ---- fused cell update: 64 b x 32 j = 2048 cells, 8 per thread ----
#pragma unroll
    for (int i = 0; i < 8; i++) {
        int idx = tid + i * 256;
        int bl = idx >> 5, jl = idx & 31;
        float gi = sE[bl * PE + jl];
        float gf = sE[bl * PE + 32 + jl];
        float gg = sE[bl * PE + 64 + jl];
        float go = sE[bl * PE + 96 + jl];
        int b = b0 + bl, j = j0 + jl;
        size_t gxo = ((size_t)b * LL + t) * G4 + j;
        float i_ = sigf(gi + gx[gxo]);
        float f_ = sigf(gf + gx[gxo + 256]);
        float g_ = tanhf(gg + gx[gxo + 512]);
        float o_ = sigf(go + gx[gxo + 768]);
        int ci = b * LHID + j;
        float cn = f_ * c[ci] + i_ * g_;
        c[ci] = cn;
        float hn = o_ * tanhf(cn);
        hsum[ci] += hn;
        __nv_bfloat16 hh = __float2bfloat16(hn);
        hnextE[(size_t)b * 512 + j]       = hh;
        hnextE[(size_t)b * 512 + 256 + j] = __float2bfloat16(hn - __bfloat162float(hh));
    }
}

// =====================================================================
// conv2/3/4 + mlp (unchanged — pass)
// =====================================================================
__global__ __launch_bounds__(256) void conv2_kernel(
    const float* __restrict__ in, const float* __restrict__ w,
    const float* __restrict__ bias, float* __restrict__ out)
{
    extern __shared__ float smf[];
    float* xs = smf;
    float* ws = smf + 32 * 69;
    const int b = blockIdx.x;
    const int tid = threadIdx.x;
    const int lane = tid & 31;
    const int cog  = tid >> 5;

    float acc[8][2];
#pragma unroll
    for (int j = 0; j < 8; j++) { acc[j][0] = 0.f; acc[j][1] = 0.f; }

    const float* ib = in + (size_t)b * 256 * 64;

    for (int ci0 = 0; ci0 < 256; ci0 += 32) {
        for (int idx = tid; idx < 32 * 68; idx += 256) {
            int cil = idx / 68, s = idx - cil * 68;
            int p = s - 2;
            xs[cil * 69 + s] =
                (p >= 0 && p < 64) ? ib[(size_t)(ci0 + cil) * 64 + p] : 0.f;
        }
        for (int idx = tid; idx < 64 * 160; idx += 256) {
            int col = idx / 160, r = idx - col * 160;
            ws[idx] = w[(size_t)col * (256 * 5) + ci0 * 5 + r];
        }
        __syncthreads();

        for (int ci = 0; ci < 32; ci++) {
            const float* xr = &xs[ci * 69 + lane];
            const float* wr = &ws[cog * 160 + ci * 5];
#pragma unroll
            for (int kw = 0; kw < 5; kw++) {
                float xv0 = xr[kw];
                float xv1 = xr[kw + 32];
#pragma unroll
                for (int j = 0; j < 8; j++) {
                    float wv = wr[j * (8 * 160) + kw];
                    acc[j][0] += wv * xv0;
                    acc[j][1] += wv * xv1;
                }
            }
        }
        __syncthreads();
    }

#pragma unroll
    for (int j = 0; j < 8; j++) {
        int co = cog + 8 * j;
        float bv = bias[co];
#pragma unroll
        for (int i = 0; i < 2; i++) {
            float v = acc[j][i] + bv;
            float o = __shfl_xor_sync(0xffffffffu, v, 1);
            float m = fmaxf(v, o);
            if (!(lane & 1)) {
                int q = (lane >> 1) + 16 * i;
                out[(size_t)b * 64 * 32 + (size_t)co * 32 + q] = fmaxf(m, 0.f);
            }
        }
    }
}

__global__ __launch_bounds__(256) void conv3_kernel(
    const float* __restrict__ in, const float* __restrict__ w,
    const float* __restrict__ bias, float* __restrict__ out)
{
    extern __shared__ float smf[];
    float* xs = smf;
    float* ws = smf + 64 * 37;
    const int b   = blockIdx.x;
    const int co0 = blockIdx.y * 128;
    const int tid = threadIdx.x;
    const int lane = tid & 31;
    const int cog  = tid >> 5;

    float acc[16];
#pragma unroll
    for (int j = 0; j < 16; j++) acc[j] = 0.f;

    const float* ib = in + (size_t)b * 64 * 32;

    for (int idx = tid; idx < 64 * 34; idx += 256) {
        int cil = idx / 34, s = idx - cil * 34;
        int p = s - 1;
        xs[cil * 37 + s] = (p >= 0 && p < 32) ? ib[(size_t)cil * 32 + p] : 0.f;
    }
    for (int idx = tid; idx < 128 * 192; idx += 256) {
        int col = idx / 192, r = idx - col * 192;
        ws[idx] = w[(size_t)(co0 + col) * 192 + r];
    }
    __syncthreads();

    for (int ci = 0; ci < 64; ci++) {
        const float* xr = &xs[ci * 37 + lane];
        float xv0 = xr[0], xv1 = xr[1], xv2 = xr[2];
        const float* wr = &ws[cog * 192 + ci * 3];
#pragma unroll
        for (int j = 0; j < 16; j++) {
            const float* wj = wr + j * (8 * 192);
            acc[j] += wj[0] * xv0 + wj[1] * xv1 + wj[2] * xv2;
        }
    }

#pragma unroll
    for (int j = 0; j < 16; j++) {
        int co = co0 + cog + 8 * j;
        float v = acc[j] + bias[co];
        float o = __shfl_xor_sync(0xffffffffu, v, 1);
        float m = fmaxf(v, o);
        if (!(lane & 1)) {
            int q = lane >> 1;
            out[(size_t)b * 256 * 16 + (size_t)co * 16 + q] = fmaxf(m, 0.f);
        }
    }
}

__global__ __launch_bounds__(256) void conv4_kernel(
    const float* __restrict__ in, const float* __restrict__ w,
    const float* __restrict__ bias, float* __restrict__ out)
{
    __shared__ float xsh[4096];
    __shared__ float wsh[4096];
    int b = blockIdx.x, tid = threadIdx.x;
    const float* ib = in + (size_t)b * 4096;
    for (int i = tid; i < 4096; i += 256) { xsh[i] = ib[i]; wsh[i] = w[i]; }
    __syncthreads();
    int co = tid >> 4, p = tid & 15;
    float acc = bias[co];
#pragma unroll 8
    for (int ci = 0; ci < 256; ci++)
        acc += xsh[ci * 16 + p] * wsh[co * 256 + ci];
    out[(size_t)b * 256 + co * 16 + p] = fmaxf(acc, 0.f);
}

__global__ __launch_bounds__(128) void mlp_kernel(
    const float* __restrict__ hsum, const float* __restrict__ feat,
    const float* __restrict__ w1, const float* __restrict__ b1,
    const float* __restrict__ w2, const float* __restrict__ b2,
    const float* __restrict__ w3, const float* __restrict__ b3,
    float* __restrict__ out)
{
    __shared__ float zin[512];
    __shared__ float z1[128];
    __shared__ float z2[32];
    int b = blockIdx.x, tid = threadIdx.x;
    for (int i = tid; i < 256; i += 128) {
        zin[i]       = hsum[(size_t)b * 256 + i] * (1.f / 128.f);
        zin[256 + i] = feat[(size_t)b * 256 + i];
    }
    __syncthreads();
    {
        const float* wr = w1 + (size_t)tid * 512;
        float acc = 0.f;
#pragma unroll 4
        for (int k = 0; k < 512; k += 4) {
            float4 wv = *(const float4*)(wr + k);
            float4 xv = *(const float4*)(&zin[k]);
            acc += wv.x * xv.x + wv.y * xv.y + wv.z * xv.z + wv.w * xv.w;
        }
        z1[tid] = fmaxf(acc + b1[tid], 0.f);
    }
    __syncthreads();
    if (tid < 32) {
        const float* wr = w2 + (size_t)tid * 128;
        float acc = 0.f;
#pragma unroll
        for (int k = 0; k < 128; k += 4) {
            float4 wv = *(const float4*)(wr + k);
            float4 xv = *(const float4*)(&z1[k]);
            acc += wv.x * xv.x + wv.y * xv.y + wv.z * xv.z + wv.w * xv.w;
        }
        z2[tid] = fmaxf(acc + b2[tid], 0.f);
    }
    __syncthreads();
    if (tid < 2) {
        const float* wr = w3 + (size_t)tid * 32;
        float acc = 0.f;
#pragma unroll
        for (int k = 0; k < 32; k++) acc += wr[k] * z2[k];
        out[(size_t)b * 2 + tid] = fmaxf(acc + b3[tid], 0.f);
    }
}

// =====================================================================
// host launcher
// =====================================================================
extern "C" void kernel_launch(void* const* d_in, const int* in_sizes, int n_in,
                              void* d_out, int out_size)
{
    const float* x    = (const float*)d_in[0];
    const float* w_ih = (const float*)d_in[1];
    const float* w_hh = (const float*)d_in[2];
    const float* b_ih = (const float*)d_in[3];
    const float* b_hh = (const float*)d_in[4];
    const float* c1w  = (const float*)d_in[5];
    const float* c1b  = (const float*)d_in[6];
    const float* c2w  = (const float*)d_in[7];
    const float* c2b  = (const float*)d_in[8];
    const float* c3w  = (const float*)d_in[9];
    const float* c3b  = (const float*)d_in[10];
    const float* c4w  = (const float*)d_in[11];
    const float* c4b  = (const float*)d_in[12];
    const float* f1w  = (const float*)d_in[13];
    const float* f1b  = (const float*)d_in[14];
    const float* f2w  = (const float*)d_in[15];
    const float* f2b  = (const float*)d_in[16];
    const float* f3w  = (const float*)d_in[17];
    const float* f3b  = (const float*)d_in[18];
    float* out = (float*)d_out;

    float *gatesx, *c, *hsum, *y1, *y2, *y3, *feat;
    __nv_bfloat16 *xE, *wihE, *wc1E, *whhE, *hEA, *hEB;
    cudaGetSymbolAddress((void**)&gatesx, g_gatesx);
    cudaGetSymbolAddress((void**)&xE,     g_xE);
    cudaGetSymbolAddress((void**)&wihE,   g_wihE);
    cudaGetSymbolAddress((void**)&wc1E,   g_wc1E);
    cudaGetSymbolAddress((void**)&whhE,   g_whhE);
    cudaGetSymbolAddress((void**)&hEA,    g_hEA);
    cudaGetSymbolAddress((void**)&hEB,    g_hEB);
    cudaGetSymbolAddress((void**)&c,      g_c);
    cudaGetSymbolAddress((void**)&hsum,   g_hsum);
    cudaGetSymbolAddress((void**)&y1,     g_y1);
    cudaGetSymbolAddress((void**)&y2,     g_y2);
    cudaGetSymbolAddress((void**)&y3,     g_y3);
    cudaGetSymbolAddress((void**)&feat,   g_feat);

    const int SM2 = (32 * 69 + 64 * 160) * 4;
    const int SM3 = (64 * 37 + 128 * 192) * 4;
    cudaFuncSetAttribute(conv2_kernel, cudaFuncAttributeMaxDynamicSharedMemorySize, SM2);
    cudaFuncSetAttribute(conv3_kernel, cudaFuncAttributeMaxDynamicSharedMemorySize, SM3);
    cudaFuncSetAttribute(gemm_mma, cudaFuncAttributeMaxDynamicSharedMemorySize, SMEMB);
    cudaFuncSetAttribute(lstm_step_mma, cudaFuncAttributeMaxDynamicSharedMemorySize, SML);

    // ---- bf16 hi/lo expansions ----
    expand_hl<<<(BB * LL * 192 + 255) / 256, 256>>>(x, xE, BB * LL * 192);
    expand_hl<<<(G4 * 192 + 255) / 256, 256>>>(w_ih, wihE, G4 * 192);
    expand_c1w<<<(256 * 768 + 255) / 256, 256>>>(c1w, wc1E);
    expand_whh<<<(1024 * 256 + 255) / 256, 256>>>(w_hh, whhE);

    // ---- conv1 via 7 accumulated HMMA GEMMs (kw-inner, 252 chunks) ----
    gemm_mma<<<dim3(2, BB), 256, SMEMB>>>(
        xE, wc1E, nullptr, nullptr, c1b, y1, 1, 7 * 36);

    // ---- rest of CNN ----
    conv2_kernel<<<BB, 256, SM2>>>(y1, c2w, c2b, y2);
    conv3_kernel<<<dim3(BB, 2), 256, SM3>>>(y2, c3w, c3b, y3);
    conv4_kernel<<<BB, 256>>>(y3, c4w, c4b, feat);

    // ---- input projection via HMMA (36 chunks) ----
    gemm_mma<<<dim3(G4 / 128, (BB * LL) / 128), 256, SMEMB>>>(
        xE, wihE, b_ih, b_hh, nullptr, gatesx, 0, 36);

    // ---- LSTM recurrence: HMMA fused step ----
    lstm_init_kernel<<<BB, 256>>>(hEA, c, hsum);
    for (int t = 0; t < LL; t++) {
        const __nv_bfloat16* hp = (t & 1) ? hEB : hEA;
        __nv_bfloat16*       hn = (t & 1) ? hEA : hEB;
        lstm_step_mma<<<dim3(8, 8), 256, SML>>>(hp, hn, c, hsum, whhE, gatesx, t);
    }

    // ---- MLP head ----
    mlp_kernel<<<BB, 128>>>(hsum, feat, f1w, f1b, f2w, f2b, f3w, f3b, out);
}